// round 1
// baseline (speedup 1.0000x reference)
#include <cuda_runtime.h>
#include <math.h>

#define LAYERS 12
#define BB 8
#define SS 512
#define HH 768
#define NHD 12
#define DHD 64
#define FFD 3072
#define M_TOK (BB*SS)   // 4096

// ---------------- scratch (static device arrays; no allocation) -------------
__device__ float g_h[M_TOK*HH];
__device__ float g_q[M_TOK*HH];
__device__ float g_k[M_TOK*HH];
__device__ float g_v[M_TOK*HH];
__device__ float g_ctx[M_TOK*HH];
__device__ float g_attn[M_TOK*HH];
__device__ float g_tmp[M_TOK*HH];
__device__ float g_inter[M_TOK*FFD];
__device__ float g_scores[BB*NHD*SS*SS];   // 25.2M floats

// ---------------- helpers ---------------------------------------------------
__inline__ __device__ float warpSum(float v){
    #pragma unroll
    for(int o=16;o;o>>=1) v += __shfl_xor_sync(0xffffffffu, v, o);
    return v;
}
__inline__ __device__ float warpMax(float v){
    #pragma unroll
    for(int o=16;o;o>>=1) v = fmaxf(v, __shfl_xor_sync(0xffffffffu, v, o));
    return v;
}
__device__ __forceinline__ float gelu_exact(float x){
    return 0.5f * x * (1.0f + erff(x * 0.70710678118654752440f));
}

__global__ void copy_kernel(float* __restrict__ dst, const float* __restrict__ src, int n){
    int i = blockIdx.x*blockDim.x + threadIdx.x;
    if(i < n) dst[i] = src[i];
}

// ---------------- SGEMM: C[M,N] = A[M,K] @ W[K,N] + bias[N] (opt GELU) ------
// BM=BN=128, BK=16, 256 threads, 8x8 per thread. All dims divisible.
template<bool GELU>
__global__ __launch_bounds__(256)
void sgemm_bias(const float* __restrict__ A, const float* __restrict__ W,
                const float* __restrict__ bias, float* __restrict__ C,
                int M, int N, int K)
{
    __shared__ float As[16][132];   // [k][m], padded
    __shared__ float Bs[16][128];   // [k][n]

    const int n0 = blockIdx.x * 128;
    const int m0 = blockIdx.y * 128;
    const int tid = threadIdx.x;
    const int tx = tid & 15;
    const int ty = tid >> 4;

    float acc[8][8];
    #pragma unroll
    for(int i=0;i<8;i++)
        #pragma unroll
        for(int j=0;j<8;j++) acc[i][j] = 0.f;

    for(int kt = 0; kt < K; kt += 16){
        // A tile: 128 rows x 16 cols
        #pragma unroll
        for(int l=0;l<2;l++){
            int f   = tid + l*256;        // 0..511 float4 slots
            int row = f >> 2;
            int kc4 = f & 3;
            float4 va = *(const float4*)(A + (size_t)(m0+row)*K + kt + kc4*4);
            As[kc4*4+0][row] = va.x;
            As[kc4*4+1][row] = va.y;
            As[kc4*4+2][row] = va.z;
            As[kc4*4+3][row] = va.w;
        }
        // B tile: 16 rows x 128 cols
        #pragma unroll
        for(int l=0;l<2;l++){
            int f   = tid + l*256;
            int row = f >> 5;
            int c4  = f & 31;
            *(float4*)(&Bs[row][c4*4]) =
                *(const float4*)(W + (size_t)(kt+row)*N + n0 + c4*4);
        }
        __syncthreads();

        #pragma unroll
        for(int kk=0;kk<16;kk++){
            float a[8], b[8];
            *(float4*)(a)   = *(const float4*)(&As[kk][ty*4]);
            *(float4*)(a+4) = *(const float4*)(&As[kk][64 + ty*4]);
            *(float4*)(b)   = *(const float4*)(&Bs[kk][tx*4]);
            *(float4*)(b+4) = *(const float4*)(&Bs[kk][64 + tx*4]);
            #pragma unroll
            for(int i=0;i<8;i++)
                #pragma unroll
                for(int j=0;j<8;j++)
                    acc[i][j] = fmaf(a[i], b[j], acc[i][j]);
        }
        __syncthreads();
    }

    // epilogue
    #pragma unroll
    for(int ih=0; ih<2; ih++){
        #pragma unroll
        for(int i=0;i<4;i++){
            int row = m0 + ih*64 + ty*4 + i;
            #pragma unroll
            for(int jh=0; jh<2; jh++){
                int col = n0 + jh*64 + tx*4;
                float4 bv = *(const float4*)(bias + col);
                float4 r;
                r.x = acc[ih*4+i][jh*4+0] + bv.x;
                r.y = acc[ih*4+i][jh*4+1] + bv.y;
                r.z = acc[ih*4+i][jh*4+2] + bv.z;
                r.w = acc[ih*4+i][jh*4+3] + bv.w;
                if(GELU){
                    r.x = gelu_exact(r.x); r.y = gelu_exact(r.y);
                    r.z = gelu_exact(r.z); r.w = gelu_exact(r.w);
                }
                *(float4*)(C + (size_t)row*N + col) = r;
            }
        }
    }
}

// ---------------- attention scores: S = Q K^T / 8 + mask --------------------
// grid (8 ktile, 8 qtile, 96 bh), 256 threads, 64x64 tile, K=64 full.
__global__ __launch_bounds__(256)
void attn_scores(const float* __restrict__ Q, const float* __restrict__ K,
                 const float* __restrict__ mask, float* __restrict__ scores)
{
    __shared__ float Qst[64][68];  // [d][m]
    __shared__ float Kst[64][68];  // [d][n]

    const int bh   = blockIdx.z;
    const int b    = bh / NHD;
    const int head = bh % NHD;
    const int q0   = blockIdx.y * 64;
    const int n0   = blockIdx.x * 64;
    const int tid  = threadIdx.x;
    const int tx   = tid & 15;
    const int ty   = tid >> 4;

    const float* Qb = Q + (size_t)(b*SS + q0)*HH + head*DHD;
    const float* Kb = K + (size_t)(b*SS + n0)*HH + head*DHD;

    #pragma unroll
    for(int l=0;l<4;l++){
        int f   = tid + l*256;   // 0..1023 float4 slots
        int row = f >> 4;        // 0..63
        int c4  = f & 15;        // 0..15
        float4 vq = *(const float4*)(Qb + (size_t)row*HH + c4*4);
        float4 vk = *(const float4*)(Kb + (size_t)row*HH + c4*4);
        Qst[c4*4+0][row]=vq.x; Qst[c4*4+1][row]=vq.y;
        Qst[c4*4+2][row]=vq.z; Qst[c4*4+3][row]=vq.w;
        Kst[c4*4+0][row]=vk.x; Kst[c4*4+1][row]=vk.y;
        Kst[c4*4+2][row]=vk.z; Kst[c4*4+3][row]=vk.w;
    }
    __syncthreads();

    float acc[4][4];
    #pragma unroll
    for(int i=0;i<4;i++)
        #pragma unroll
        for(int j=0;j<4;j++) acc[i][j]=0.f;

    #pragma unroll 4
    for(int k=0;k<64;k++){
        float a[4], bb[4];
        *(float4*)a  = *(const float4*)(&Qst[k][ty*4]);
        *(float4*)bb = *(const float4*)(&Kst[k][tx*4]);
        #pragma unroll
        for(int i=0;i<4;i++)
            #pragma unroll
            for(int j=0;j<4;j++)
                acc[i][j] = fmaf(a[i], bb[j], acc[i][j]);
    }

    float4 mv = *(const float4*)(mask + b*SS + n0 + tx*4);
    #pragma unroll
    for(int i=0;i<4;i++){
        float4 r;
        r.x = acc[i][0]*0.125f + mv.x;
        r.y = acc[i][1]*0.125f + mv.y;
        r.z = acc[i][2]*0.125f + mv.z;
        r.w = acc[i][3]*0.125f + mv.w;
        *(float4*)(scores + ((size_t)bh*SS + q0 + ty*4 + i)*SS + n0 + tx*4) = r;
    }
}

// ---------------- softmax over rows of 512 ----------------------------------
__global__ __launch_bounds__(128)
void softmax_rows(float* __restrict__ scores)
{
    float* p = scores + (size_t)blockIdx.x * SS;
    const int t = threadIdx.x;
    float v[4];
    float mx = -1e30f;
    #pragma unroll
    for(int i=0;i<4;i++){ v[i] = p[t + i*128]; mx = fmaxf(mx, v[i]); }

    __shared__ float sm[4];
    float wmx = warpMax(mx);
    int warp = t >> 5, lane = t & 31;
    if(lane==0) sm[warp] = wmx;
    __syncthreads();
    float bm = fmaxf(fmaxf(sm[0],sm[1]), fmaxf(sm[2],sm[3]));

    float s = 0.f;
    #pragma unroll
    for(int i=0;i<4;i++){ v[i] = __expf(v[i] - bm); s += v[i]; }
    float ws = warpSum(s);
    __syncthreads();
    if(lane==0) sm[warp] = ws;
    __syncthreads();
    float tot = sm[0]+sm[1]+sm[2]+sm[3];
    float inv = 1.0f / tot;
    #pragma unroll
    for(int i=0;i<4;i++) p[t + i*128] = v[i] * inv;
}

// ---------------- ctx = P @ V ------------------------------------------------
// grid (8 qtile, 96 bh), 256 threads, out tile 64(q) x 64(d), K=512 in 32-chunks
__global__ __launch_bounds__(256)
void attn_ctx(const float* __restrict__ P, const float* __restrict__ V,
              float* __restrict__ ctx)
{
    __shared__ float Ps[64][36];   // [q][k]
    __shared__ float Vs[32][64];   // [k][d]

    const int bh   = blockIdx.y;
    const int b    = bh / NHD;
    const int head = bh % NHD;
    const int q0   = blockIdx.x * 64;
    const int tid  = threadIdx.x;
    const int tx   = tid & 15;
    const int ty   = tid >> 4;

    const float* Pb = P + ((size_t)bh*SS + q0) * SS;
    const float* Vb = V + (size_t)(b*SS)*HH + head*DHD;

    float acc[4][4];
    #pragma unroll
    for(int i=0;i<4;i++)
        #pragma unroll
        for(int j=0;j<4;j++) acc[i][j]=0.f;

    for(int kt=0; kt<SS; kt+=32){
        // P: 64 x 32
        #pragma unroll
        for(int l=0;l<2;l++){
            int f   = tid + l*256;   // 0..511 float4 slots
            int row = f >> 3;        // 0..63
            int c4  = f & 7;         // 0..7
            *(float4*)(&Ps[row][c4*4]) =
                *(const float4*)(Pb + (size_t)row*SS + kt + c4*4);
        }
        // V: 32 x 64
        #pragma unroll
        for(int l=0;l<2;l++){
            int f   = tid + l*256;
            int row = f >> 4;        // 0..31
            int c4  = f & 15;        // 0..15
            *(float4*)(&Vs[row][c4*4]) =
                *(const float4*)(Vb + (size_t)(kt+row)*HH + c4*4);
        }
        __syncthreads();

        #pragma unroll 4
        for(int k=0;k<32;k++){
            float bb[4];
            *(float4*)bb = *(const float4*)(&Vs[k][tx*4]);
            float a0 = Ps[ty*4+0][k];
            float a1 = Ps[ty*4+1][k];
            float a2 = Ps[ty*4+2][k];
            float a3 = Ps[ty*4+3][k];
            #pragma unroll
            for(int j=0;j<4;j++){
                acc[0][j] = fmaf(a0, bb[j], acc[0][j]);
                acc[1][j] = fmaf(a1, bb[j], acc[1][j]);
                acc[2][j] = fmaf(a2, bb[j], acc[2][j]);
                acc[3][j] = fmaf(a3, bb[j], acc[3][j]);
            }
        }
        __syncthreads();
    }

    #pragma unroll
    for(int i=0;i<4;i++){
        float4 r; r.x=acc[i][0]; r.y=acc[i][1]; r.z=acc[i][2]; r.w=acc[i][3];
        *(float4*)(ctx + (size_t)(b*SS + q0 + ty*4 + i)*HH + head*DHD + tx*4) = r;
    }
}

// ---------------- add residual + layernorm -----------------------------------
__global__ __launch_bounds__(256)
void add_layernorm(const float* __restrict__ x, const float* __restrict__ res,
                   const float* __restrict__ g, const float* __restrict__ bta,
                   float* __restrict__ out)
{
    const int tok = blockIdx.x;
    const float* xp = x   + (size_t)tok*HH;
    const float* rp = res + (size_t)tok*HH;
    float* op       = out + (size_t)tok*HH;
    const int t = threadIdx.x;

    float v[3];
    float s = 0.f, sq = 0.f;
    #pragma unroll
    for(int i=0;i<3;i++){
        int c = t + i*256;
        float val = xp[c] + rp[c];
        v[i] = val; s += val; sq += val*val;
    }

    __shared__ float rs[8], rq[8];
    float ws = warpSum(s), wq = warpSum(sq);
    int warp = t >> 5, lane = t & 31;
    if(lane==0){ rs[warp]=ws; rq[warp]=wq; }
    __syncthreads();
    if(warp==0){
        float a = (lane<8)? rs[lane] : 0.f;
        float bq2 = (lane<8)? rq[lane] : 0.f;
        a = warpSum(a); bq2 = warpSum(bq2);
        if(lane==0){ rs[0]=a; rq[0]=bq2; }
    }
    __syncthreads();
    const float mean = rs[0] * (1.0f/768.0f);
    const float var  = rq[0] * (1.0f/768.0f) - mean*mean;
    const float inv  = rsqrtf(var + 1e-12f);

    #pragma unroll
    for(int i=0;i<3;i++){
        int c = t + i*256;
        op[c] = (v[i] - mean) * inv * g[c] + bta[c];
    }
}

// ---------------- launch ------------------------------------------------------
extern "C" void kernel_launch(void* const* d_in, const int* in_sizes, int n_in,
                              void* d_out, int out_size)
{
    const float* hs   = (const float*)d_in[0];
    const float* mask = (const float*)d_in[1];
    const float* Wq   = (const float*)d_in[2];
    const float* bq   = (const float*)d_in[3];
    const float* Wk   = (const float*)d_in[4];
    const float* bk   = (const float*)d_in[5];
    const float* Wv   = (const float*)d_in[6];
    const float* bv   = (const float*)d_in[7];
    const float* Wo   = (const float*)d_in[8];
    const float* bo   = (const float*)d_in[9];
    const float* g1   = (const float*)d_in[10];
    const float* b1   = (const float*)d_in[11];
    const float* Wi   = (const float*)d_in[12];
    const float* bi   = (const float*)d_in[13];
    const float* Wo2  = (const float*)d_in[14];
    const float* bo2  = (const float*)d_in[15];
    const float* g2   = (const float*)d_in[16];
    const float* b2   = (const float*)d_in[17];

    float *h, *q, *k, *v, *ctx, *attn, *tmp, *inter, *scores;
    cudaGetSymbolAddress((void**)&h,      g_h);
    cudaGetSymbolAddress((void**)&q,      g_q);
    cudaGetSymbolAddress((void**)&k,      g_k);
    cudaGetSymbolAddress((void**)&v,      g_v);
    cudaGetSymbolAddress((void**)&ctx,    g_ctx);
    cudaGetSymbolAddress((void**)&attn,   g_attn);
    cudaGetSymbolAddress((void**)&tmp,    g_tmp);
    cudaGetSymbolAddress((void**)&inter,  g_inter);
    cudaGetSymbolAddress((void**)&scores, g_scores);

    const int nH = M_TOK*HH;
    copy_kernel<<<(nH+255)/256, 256>>>(h, hs, nH);

    dim3 gProj(HH/128,  M_TOK/128);   // (6, 32)
    dim3 gFF1 (FFD/128, M_TOK/128);   // (24, 32)

    for(int l=0; l<LAYERS; l++){
        const float* lWq  = Wq  + (size_t)l*HH*HH;
        const float* lWk  = Wk  + (size_t)l*HH*HH;
        const float* lWv  = Wv  + (size_t)l*HH*HH;
        const float* lWo  = Wo  + (size_t)l*HH*HH;
        const float* lWi  = Wi  + (size_t)l*HH*FFD;
        const float* lWo2 = Wo2 + (size_t)l*FFD*HH;
        const float* lbq  = bq  + (size_t)l*HH;
        const float* lbk  = bk  + (size_t)l*HH;
        const float* lbv  = bv  + (size_t)l*HH;
        const float* lbo  = bo  + (size_t)l*HH;
        const float* lbi  = bi  + (size_t)l*FFD;
        const float* lbo2 = bo2 + (size_t)l*HH;
        const float* lg1  = g1  + (size_t)l*HH;
        const float* lb1  = b1  + (size_t)l*HH;
        const float* lg2  = g2  + (size_t)l*HH;
        const float* lb2  = b2  + (size_t)l*HH;

        sgemm_bias<false><<<gProj, 256>>>(h, lWq, lbq, q, M_TOK, HH, HH);
        sgemm_bias<false><<<gProj, 256>>>(h, lWk, lbk, k, M_TOK, HH, HH);
        sgemm_bias<false><<<gProj, 256>>>(h, lWv, lbv, v, M_TOK, HH, HH);

        attn_scores<<<dim3(8,8,BB*NHD), 256>>>(q, k, mask, scores);
        softmax_rows<<<BB*NHD*SS, 128>>>(scores);
        attn_ctx<<<dim3(8,BB*NHD), 256>>>(scores, v, ctx);

        sgemm_bias<false><<<gProj, 256>>>(ctx, lWo, lbo, tmp, M_TOK, HH, HH);
        add_layernorm<<<M_TOK, 256>>>(tmp, h, lg1, lb1, attn);

        sgemm_bias<true ><<<gFF1, 256>>>(attn, lWi, lbi, inter, M_TOK, FFD, HH);
        sgemm_bias<false><<<gProj, 256>>>(inter, lWo2, lbo2, tmp, M_TOK, HH, FFD);
        add_layernorm<<<M_TOK, 256>>>(tmp, attn, lg2, lb2, h);
    }

    copy_kernel<<<(nH+255)/256, 256>>>((float*)d_out, h, nH);
}

// round 3
// speedup vs baseline: 1.8062x; 1.8062x over previous
#include <cuda_runtime.h>
#include <math.h>
#include <stdint.h>

#define LAYERS 12
#define BB 8
#define SS 512
#define HH 768
#define NHD 12
#define DHD 64
#define FFD 3072
#define M_TOK (BB*SS)   // 4096

// ---------------- scratch (static device arrays; no allocation) -------------
__device__ float g_h[M_TOK*HH];
__device__ float g_q[M_TOK*HH];
__device__ float g_k[M_TOK*HH];
__device__ float g_v[M_TOK*HH];
__device__ float g_ctx[M_TOK*HH];
__device__ float g_attn[M_TOK*HH];
__device__ float g_tmp[M_TOK*HH];
__device__ float g_round[M_TOK*HH];
__device__ float g_inter[M_TOK*FFD];
__device__ float g_scores[BB*NHD*SS*SS];

// transposed (and tf32-rounded) weights: WT[N][K]
__device__ float g_wqT [LAYERS*HH*HH];
__device__ float g_wkT [LAYERS*HH*HH];
__device__ float g_wvT [LAYERS*HH*HH];
__device__ float g_woT [LAYERS*HH*HH];
__device__ float g_wiT [LAYERS*HH*FFD];
__device__ float g_wo2T[LAYERS*FFD*HH];

// ---------------- small helpers ---------------------------------------------
__inline__ __device__ float warpSum(float v){
    #pragma unroll
    for(int o=16;o;o>>=1) v += __shfl_xor_sync(0xffffffffu, v, o);
    return v;
}
__inline__ __device__ float warpMax(float v){
    #pragma unroll
    for(int o=16;o;o>>=1) v = fmaxf(v, __shfl_xor_sync(0xffffffffu, v, o));
    return v;
}
__device__ __forceinline__ float gelu_exact(float x){
    return 0.5f * x * (1.0f + erff(x * 0.70710678118654752440f));
}
__device__ __forceinline__ float to_tf32(float x){
    uint32_t r;
    asm("cvt.rn.tf32.f32 %0, %1;" : "=r"(r) : "f"(x));
    return __uint_as_float(r);
}
__device__ __forceinline__ uint32_t s2u(const void* p){
    uint32_t a;
    asm("{ .reg .u64 t; cvta.to.shared.u64 t, %1; cvt.u32.u64 %0, t; }" : "=r"(a) : "l"(p));
    return a;
}

#define CP_ASYNC16(dst, src) \
    asm volatile("cp.async.cg.shared.global [%0], [%1], 16;" :: "r"(dst), "l"(src))
#define CP_COMMIT() asm volatile("cp.async.commit_group;")
#define CP_WAIT(N)  asm volatile("cp.async.wait_group %0;" :: "n"(N) : "memory")

// tf32 mma: D += A(16x8 row) * B(8x8 col)
__device__ __forceinline__ void mma_tf32(float* d, const uint32_t* a, const uint32_t* b){
    asm volatile(
        "mma.sync.aligned.m16n8k8.row.col.f32.tf32.tf32.f32 "
        "{%0,%1,%2,%3}, {%4,%5,%6,%7}, {%8,%9}, {%0,%1,%2,%3};"
        : "+f"(d[0]), "+f"(d[1]), "+f"(d[2]), "+f"(d[3])
        : "r"(a[0]), "r"(a[1]), "r"(a[2]), "r"(a[3]), "r"(b[0]), "r"(b[1]));
}

// ---------------- misc elementwise kernels ------------------------------------
__global__ void copy_kernel(float* __restrict__ dst, const float* __restrict__ src, int n){
    int i = blockIdx.x*blockDim.x + threadIdx.x;
    if(i < n) dst[i] = src[i];
}
__global__ void round_tf32_kernel(float* __restrict__ dst, const float* __restrict__ src, int n){
    int i = blockIdx.x*blockDim.x + threadIdx.x;
    if(i < n) dst[i] = to_tf32(src[i]);
}

// transpose + round: W [L][K][N] -> WT [L][N][K]
__global__ void transpose_round(const float* __restrict__ W, float* __restrict__ WT,
                                int K, int N){
    __shared__ float ts[32][33];
    const int l = blockIdx.z;
    const float* Wl = W + (size_t)l*K*N;
    float* WTl = WT + (size_t)l*K*N;
    const int n0 = blockIdx.x*32, k0 = blockIdx.y*32;
    const int tx = threadIdx.x, ty = threadIdx.y;  // 32 x 8
    #pragma unroll
    for(int i=0;i<4;i++)
        ts[ty+i*8][tx] = Wl[(size_t)(k0+ty+i*8)*N + n0 + tx];
    __syncthreads();
    #pragma unroll
    for(int i=0;i<4;i++)
        WTl[(size_t)(n0+ty+i*8)*K + k0 + tx] = to_tf32(ts[tx][ty+i*8]);
}

// ---------------- TF32 tensor-core GEMM: C[M,N] = A[M,K] @ WT[N,K]^T + bias ---
// CTA tile 128x128, BK=32, 256 threads (8 warps), warp tile 32x64.
// 3-stage cp.async pipeline. Smem rows padded to 40 floats (stride ≡ 8 mod 32)
// so every mma fragment LDS is bank-conflict-free.
#define BK 32
#define PAD 40
#define TILEF (128*PAD)            // floats per tile buffer
#define GSTAGES 3
#define GSMEM (2*GSTAGES*TILEF*4)  // 122880 bytes

template<bool GELU, bool ROUND>
__global__ __launch_bounds__(256)
void mma_gemm(const float* __restrict__ A, const float* __restrict__ Wt,
              const float* __restrict__ bias, float* __restrict__ C,
              int N, int K)
{
    extern __shared__ float sm[];
    float* Asm = sm;                    // [GSTAGES][128][PAD]
    float* Wsm = sm + GSTAGES*TILEF;    // [GSTAGES][128][PAD]

    const int tid  = threadIdx.x;
    const int wid  = tid >> 5;
    const int lane = tid & 31;
    const int m0 = blockIdx.y * 128;
    const int n0 = blockIdx.x * 128;
    const int wm = (wid >> 1) * 32;     // 4 warps along M
    const int wn = (wid & 1) * 64;      // 2 warps along N
    const int g  = lane >> 2;           // 0..7
    const int t4 = lane & 3;            // 0..3
    const int KT = K / BK;

    const float* Ag = A  + (size_t)m0 * K;
    const float* Wg = Wt + (size_t)n0 * K;

    auto load_tile = [&](int t){
        const int s = t % GSTAGES;
        float* as = Asm + s*TILEF;
        float* ws = Wsm + s*TILEF;
        #pragma unroll
        for(int l=0;l<4;l++){
            const int c   = tid + l*256;   // 0..1023 float4 chunks (128 rows x 8)
            const int row = c >> 3;
            const int k4  = c & 7;
            CP_ASYNC16(s2u(as + row*PAD + k4*4), Ag + (size_t)row*K + t*BK + k4*4);
            CP_ASYNC16(s2u(ws + row*PAD + k4*4), Wg + (size_t)row*K + t*BK + k4*4);
        }
        CP_COMMIT();
    };

    float acc[2][8][4];
    #pragma unroll
    for(int mi=0;mi<2;mi++)
        #pragma unroll
        for(int ni=0;ni<8;ni++)
            #pragma unroll
            for(int r=0;r<4;r++) acc[mi][ni][r] = 0.f;

    load_tile(0);
    load_tile(1);

    for(int t=0; t<KT; t++){
        if (t < KT-1) CP_WAIT(1); else CP_WAIT(0);
        __syncthreads();

        const float* as = Asm + (t % GSTAGES)*TILEF;
        const float* ws = Wsm + (t % GSTAGES)*TILEF;

        #pragma unroll
        for(int ks=0; ks<BK/8; ks++){
            uint32_t a[2][4], b[8][2];
            #pragma unroll
            for(int mi=0; mi<2; mi++){
                const float* ap = as + (wm + mi*16 + g)*PAD + ks*8 + t4;
                a[mi][0] = __float_as_uint(ap[0]);
                a[mi][1] = __float_as_uint(ap[8*PAD]);
                a[mi][2] = __float_as_uint(ap[4]);
                a[mi][3] = __float_as_uint(ap[8*PAD + 4]);
            }
            #pragma unroll
            for(int ni=0; ni<8; ni++){
                const float* bp = ws + (wn + ni*8 + g)*PAD + ks*8 + t4;
                b[ni][0] = __float_as_uint(bp[0]);
                b[ni][1] = __float_as_uint(bp[4]);
            }
            #pragma unroll
            for(int mi=0; mi<2; mi++)
                #pragma unroll
                for(int ni=0; ni<8; ni++)
                    mma_tf32(acc[mi][ni], a[mi], b[ni]);
        }
        __syncthreads();
        if (t+2 < KT) load_tile(t+2);
    }

    // epilogue
    #pragma unroll
    for(int mi=0; mi<2; mi++){
        #pragma unroll
        for(int ni=0; ni<8; ni++){
            const int r = m0 + wm + mi*16 + g;
            const int c = n0 + wn + ni*8 + 2*t4;
            const float bx = bias[c], by = bias[c+1];
            float v0 = acc[mi][ni][0] + bx;
            float v1 = acc[mi][ni][1] + by;
            float v2 = acc[mi][ni][2] + bx;
            float v3 = acc[mi][ni][3] + by;
            if (GELU){
                v0 = gelu_exact(v0); v1 = gelu_exact(v1);
                v2 = gelu_exact(v2); v3 = gelu_exact(v3);
            }
            if (ROUND){
                v0 = to_tf32(v0); v1 = to_tf32(v1);
                v2 = to_tf32(v2); v3 = to_tf32(v3);
            }
            *(float2*)(C + (size_t)r*N + c)     = make_float2(v0, v1);
            *(float2*)(C + (size_t)(r+8)*N + c) = make_float2(v2, v3);
        }
    }
}

// ---------------- attention scores: S = Q K^T / 8 + mask ----------------------
__global__ __launch_bounds__(256)
void attn_scores(const float* __restrict__ Q, const float* __restrict__ K,
                 const float* __restrict__ mask, float* __restrict__ scores)
{
    __shared__ float Qst[64][68];
    __shared__ float Kst[64][68];

    const int bh   = blockIdx.z;
    const int b    = bh / NHD;
    const int head = bh % NHD;
    const int q0   = blockIdx.y * 64;
    const int n0   = blockIdx.x * 64;
    const int tid  = threadIdx.x;
    const int tx   = tid & 15;
    const int ty   = tid >> 4;

    const float* Qb = Q + (size_t)(b*SS + q0)*HH + head*DHD;
    const float* Kb = K + (size_t)(b*SS + n0)*HH + head*DHD;

    #pragma unroll
    for(int l=0;l<4;l++){
        int f   = tid + l*256;
        int row = f >> 4;
        int c4  = f & 15;
        float4 vq = *(const float4*)(Qb + (size_t)row*HH + c4*4);
        float4 vk = *(const float4*)(Kb + (size_t)row*HH + c4*4);
        Qst[c4*4+0][row]=vq.x; Qst[c4*4+1][row]=vq.y;
        Qst[c4*4+2][row]=vq.z; Qst[c4*4+3][row]=vq.w;
        Kst[c4*4+0][row]=vk.x; Kst[c4*4+1][row]=vk.y;
        Kst[c4*4+2][row]=vk.z; Kst[c4*4+3][row]=vk.w;
    }
    __syncthreads();

    float acc[4][4];
    #pragma unroll
    for(int i=0;i<4;i++)
        #pragma unroll
        for(int j=0;j<4;j++) acc[i][j]=0.f;

    #pragma unroll 4
    for(int k=0;k<64;k++){
        float a[4], bb2[4];
        *(float4*)a   = *(const float4*)(&Qst[k][ty*4]);
        *(float4*)bb2 = *(const float4*)(&Kst[k][tx*4]);
        #pragma unroll
        for(int i=0;i<4;i++)
            #pragma unroll
            for(int j=0;j<4;j++)
                acc[i][j] = fmaf(a[i], bb2[j], acc[i][j]);
    }

    float4 mv = *(const float4*)(mask + b*SS + n0 + tx*4);
    #pragma unroll
    for(int i=0;i<4;i++){
        float4 r;
        r.x = acc[i][0]*0.125f + mv.x;
        r.y = acc[i][1]*0.125f + mv.y;
        r.z = acc[i][2]*0.125f + mv.z;
        r.w = acc[i][3]*0.125f + mv.w;
        *(float4*)(scores + ((size_t)bh*SS + q0 + ty*4 + i)*SS + n0 + tx*4) = r;
    }
}

// ---------------- softmax over rows of 512 ------------------------------------
__global__ __launch_bounds__(128)
void softmax_rows(float* __restrict__ scores)
{
    float* p = scores + (size_t)blockIdx.x * SS;
    const int t = threadIdx.x;
    float v[4];
    float mx = -1e30f;
    #pragma unroll
    for(int i=0;i<4;i++){ v[i] = p[t + i*128]; mx = fmaxf(mx, v[i]); }

    __shared__ float sm[4];
    float wmx = warpMax(mx);
    int warp = t >> 5, lane = t & 31;
    if(lane==0) sm[warp] = wmx;
    __syncthreads();
    float bm = fmaxf(fmaxf(sm[0],sm[1]), fmaxf(sm[2],sm[3]));

    float s = 0.f;
    #pragma unroll
    for(int i=0;i<4;i++){ v[i] = __expf(v[i] - bm); s += v[i]; }
    float ws = warpSum(s);
    __syncthreads();
    if(lane==0) sm[warp] = ws;
    __syncthreads();
    float tot = sm[0]+sm[1]+sm[2]+sm[3];
    float inv = 1.0f / tot;
    #pragma unroll
    for(int i=0;i<4;i++) p[t + i*128] = v[i] * inv;
}

// ---------------- ctx = P @ V  (output rounded to tf32) ------------------------
__global__ __launch_bounds__(256)
void attn_ctx(const float* __restrict__ P, const float* __restrict__ V,
              float* __restrict__ ctx)
{
    __shared__ float Ps[64][36];
    __shared__ float Vs[32][64];

    const int bh   = blockIdx.y;
    const int b    = bh / NHD;
    const int head = bh % NHD;
    const int q0   = blockIdx.x * 64;
    const int tid  = threadIdx.x;
    const int tx   = tid & 15;
    const int ty   = tid >> 4;

    const float* Pb = P + ((size_t)bh*SS + q0) * SS;
    const float* Vb = V + (size_t)(b*SS)*HH + head*DHD;

    float acc[4][4];
    #pragma unroll
    for(int i=0;i<4;i++)
        #pragma unroll
        for(int j=0;j<4;j++) acc[i][j]=0.f;

    for(int kt=0; kt<SS; kt+=32){
        #pragma unroll
        for(int l=0;l<2;l++){
            int f   = tid + l*256;
            int row = f >> 3;
            int c4  = f & 7;
            *(float4*)(&Ps[row][c4*4]) =
                *(const float4*)(Pb + (size_t)row*SS + kt + c4*4);
        }
        #pragma unroll
        for(int l=0;l<2;l++){
            int f   = tid + l*256;
            int row = f >> 4;
            int c4  = f & 15;
            *(float4*)(&Vs[row][c4*4]) =
                *(const float4*)(Vb + (size_t)(kt+row)*HH + c4*4);
        }
        __syncthreads();

        #pragma unroll 4
        for(int k=0;k<32;k++){
            float bb2[4];
            *(float4*)bb2 = *(const float4*)(&Vs[k][tx*4]);
            float a0 = Ps[ty*4+0][k];
            float a1 = Ps[ty*4+1][k];
            float a2 = Ps[ty*4+2][k];
            float a3 = Ps[ty*4+3][k];
            #pragma unroll
            for(int j=0;j<4;j++){
                acc[0][j] = fmaf(a0, bb2[j], acc[0][j]);
                acc[1][j] = fmaf(a1, bb2[j], acc[1][j]);
                acc[2][j] = fmaf(a2, bb2[j], acc[2][j]);
                acc[3][j] = fmaf(a3, bb2[j], acc[3][j]);
            }
        }
        __syncthreads();
    }

    #pragma unroll
    for(int i=0;i<4;i++){
        float4 r;
        r.x = to_tf32(acc[i][0]); r.y = to_tf32(acc[i][1]);
        r.z = to_tf32(acc[i][2]); r.w = to_tf32(acc[i][3]);
        *(float4*)(ctx + (size_t)(b*SS + q0 + ty*4 + i)*HH + head*DHD + tx*4) = r;
    }
}

// ---------------- add residual + layernorm -------------------------------------
__global__ __launch_bounds__(256)
void add_layernorm(const float* __restrict__ x, const float* __restrict__ res,
                   const float* __restrict__ g, const float* __restrict__ bta,
                   float* __restrict__ out)
{
    const int tok = blockIdx.x;
    const float* xp = x   + (size_t)tok*HH;
    const float* rp = res + (size_t)tok*HH;
    float* op       = out + (size_t)tok*HH;
    const int t = threadIdx.x;

    float v[3];
    float s = 0.f, sq = 0.f;
    #pragma unroll
    for(int i=0;i<3;i++){
        int c = t + i*256;
        float val = xp[c] + rp[c];
        v[i] = val; s += val; sq += val*val;
    }

    __shared__ float rs[8], rq[8];
    float ws = warpSum(s), wq = warpSum(sq);
    int warp = t >> 5, lane = t & 31;
    if(lane==0){ rs[warp]=ws; rq[warp]=wq; }
    __syncthreads();
    if(warp==0){
        float a = (lane<8)? rs[lane] : 0.f;
        float bq2 = (lane<8)? rq[lane] : 0.f;
        a = warpSum(a); bq2 = warpSum(bq2);
        if(lane==0){ rs[0]=a; rq[0]=bq2; }
    }
    __syncthreads();
    const float mean = rs[0] * (1.0f/768.0f);
    const float var  = rq[0] * (1.0f/768.0f) - mean*mean;
    const float inv  = rsqrtf(var + 1e-12f);

    #pragma unroll
    for(int i=0;i<3;i++){
        int c = t + i*256;
        op[c] = (v[i] - mean) * inv * g[c] + bta[c];
    }
}

// ---------------- launch --------------------------------------------------------
extern "C" void kernel_launch(void* const* d_in, const int* in_sizes, int n_in,
                              void* d_out, int out_size)
{
    const float* hs   = (const float*)d_in[0];
    const float* mask = (const float*)d_in[1];
    const float* Wq   = (const float*)d_in[2];
    const float* bq   = (const float*)d_in[3];
    const float* Wk   = (const float*)d_in[4];
    const float* bk   = (const float*)d_in[5];
    const float* Wv   = (const float*)d_in[6];
    const float* bv   = (const float*)d_in[7];
    const float* Wo   = (const float*)d_in[8];
    const float* bo   = (const float*)d_in[9];
    const float* g1   = (const float*)d_in[10];
    const float* b1   = (const float*)d_in[11];
    const float* Wi   = (const float*)d_in[12];
    const float* bi   = (const float*)d_in[13];
    const float* Wo2  = (const float*)d_in[14];
    const float* bo2  = (const float*)d_in[15];
    const float* g2   = (const float*)d_in[16];
    const float* b2   = (const float*)d_in[17];

    float *h, *q, *k, *v, *ctx, *attn, *tmp, *inter, *scores, *rA;
    float *wqT, *wkT, *wvT, *woT, *wiT, *wo2T;
    cudaGetSymbolAddress((void**)&h,      g_h);
    cudaGetSymbolAddress((void**)&q,      g_q);
    cudaGetSymbolAddress((void**)&k,      g_k);
    cudaGetSymbolAddress((void**)&v,      g_v);
    cudaGetSymbolAddress((void**)&ctx,    g_ctx);
    cudaGetSymbolAddress((void**)&attn,   g_attn);
    cudaGetSymbolAddress((void**)&tmp,    g_tmp);
    cudaGetSymbolAddress((void**)&inter,  g_inter);
    cudaGetSymbolAddress((void**)&scores, g_scores);
    cudaGetSymbolAddress((void**)&rA,     g_round);
    cudaGetSymbolAddress((void**)&wqT,    g_wqT);
    cudaGetSymbolAddress((void**)&wkT,    g_wkT);
    cudaGetSymbolAddress((void**)&wvT,    g_wvT);
    cudaGetSymbolAddress((void**)&woT,    g_woT);
    cudaGetSymbolAddress((void**)&wiT,    g_wiT);
    cudaGetSymbolAddress((void**)&wo2T,   g_wo2T);

    cudaFuncSetAttribute(mma_gemm<false,false>, cudaFuncAttributeMaxDynamicSharedMemorySize, GSMEM);
    cudaFuncSetAttribute(mma_gemm<true,true>,   cudaFuncAttributeMaxDynamicSharedMemorySize, GSMEM);

    // transpose + tf32-round all weights
    transpose_round<<<dim3(HH/32,  HH/32,  LAYERS), dim3(32,8)>>>(Wq,  wqT,  HH,  HH);
    transpose_round<<<dim3(HH/32,  HH/32,  LAYERS), dim3(32,8)>>>(Wk,  wkT,  HH,  HH);
    transpose_round<<<dim3(HH/32,  HH/32,  LAYERS), dim3(32,8)>>>(Wv,  wvT,  HH,  HH);
    transpose_round<<<dim3(HH/32,  HH/32,  LAYERS), dim3(32,8)>>>(Wo,  woT,  HH,  HH);
    transpose_round<<<dim3(FFD/32, HH/32,  LAYERS), dim3(32,8)>>>(Wi,  wiT,  HH,  FFD);
    transpose_round<<<dim3(HH/32,  FFD/32, LAYERS), dim3(32,8)>>>(Wo2, wo2T, FFD, HH);

    const int nH = M_TOK*HH;
    copy_kernel<<<(nH+255)/256, 256>>>(h, hs, nH);

    dim3 gProj(HH/128,  M_TOK/128);   // (6, 32)
    dim3 gFF1 (FFD/128, M_TOK/128);   // (24, 32)

    for(int l=0; l<LAYERS; l++){
        const float* lbq  = bq  + (size_t)l*HH;
        const float* lbk  = bk  + (size_t)l*HH;
        const float* lbv  = bv  + (size_t)l*HH;
        const float* lbo  = bo  + (size_t)l*HH;
        const float* lbi  = bi  + (size_t)l*FFD;
        const float* lbo2 = bo2 + (size_t)l*HH;
        const float* lg1  = g1  + (size_t)l*HH;
        const float* lb1  = b1  + (size_t)l*HH;
        const float* lg2  = g2  + (size_t)l*HH;
        const float* lb2  = b2  + (size_t)l*HH;

        round_tf32_kernel<<<(nH+255)/256, 256>>>(rA, h, nH);

        mma_gemm<false,false><<<gProj, 256, GSMEM>>>(rA, wqT + (size_t)l*HH*HH, lbq, q, HH, HH);
        mma_gemm<false,false><<<gProj, 256, GSMEM>>>(rA, wkT + (size_t)l*HH*HH, lbk, k, HH, HH);
        mma_gemm<false,false><<<gProj, 256, GSMEM>>>(rA, wvT + (size_t)l*HH*HH, lbv, v, HH, HH);

        attn_scores<<<dim3(8,8,BB*NHD), 256>>>(q, k, mask, scores);
        softmax_rows<<<BB*NHD*SS, 128>>>(scores);
        attn_ctx<<<dim3(8,BB*NHD), 256>>>(scores, v, ctx);

        mma_gemm<false,false><<<gProj, 256, GSMEM>>>(ctx, woT + (size_t)l*HH*HH, lbo, tmp, HH, HH);
        add_layernorm<<<M_TOK, 256>>>(tmp, h, lg1, lb1, attn);

        round_tf32_kernel<<<(nH+255)/256, 256>>>(rA, attn, nH);
        mma_gemm<true,true><<<gFF1, 256, GSMEM>>>(rA, wiT + (size_t)l*HH*FFD, lbi, inter, FFD, HH);
        mma_gemm<false,false><<<gProj, 256, GSMEM>>>(inter, wo2T + (size_t)l*FFD*HH, lbo2, tmp, HH, FFD);
        add_layernorm<<<M_TOK, 256>>>(tmp, attn, lg2, lb2, h);
    }

    copy_kernel<<<(nH+255)/256, 256>>>((float*)d_out, h, nH);
}

// round 4
// speedup vs baseline: 2.1381x; 1.1838x over previous
#include <cuda_runtime.h>
#include <math.h>
#include <stdint.h>

#define LAYERS 12
#define BB 8
#define SS 512
#define HH 768
#define NHD 12
#define DHD 64
#define FFD 3072
#define M_TOK (BB*SS)   // 4096
#define QKVS 2304
#define KOFF 768
#define VOFF 1536

// ---------------- scratch (static device arrays; no allocation) -------------
__device__ float g_h[M_TOK*HH];
__device__ float g_qkv[M_TOK*QKVS];
__device__ float g_ctx[M_TOK*HH];
__device__ float g_attn[M_TOK*HH];
__device__ float g_tmp[M_TOK*HH];
__device__ float g_round[M_TOK*HH];
__device__ float g_inter[M_TOK*FFD];
__device__ float g_scores[BB*NHD*SS*SS];

__device__ float g_wqkvT[LAYERS*QKVS*HH];   // fused QKV weights [N=2304][K=768], permuted K
__device__ float g_bqkv [LAYERS*QKVS];
__device__ float g_woT  [LAYERS*HH*HH];
__device__ float g_wiT  [LAYERS*HH*FFD];
__device__ float g_wo2T [LAYERS*FFD*HH];

// ---------------- helpers -----------------------------------------------------
__inline__ __device__ float warpSum(float v){
    #pragma unroll
    for(int o=16;o;o>>=1) v += __shfl_xor_sync(0xffffffffu, v, o);
    return v;
}
__inline__ __device__ float warpMax(float v){
    #pragma unroll
    for(int o=16;o;o>>=1) v = fmaxf(v, __shfl_xor_sync(0xffffffffu, v, o));
    return v;
}
__device__ __forceinline__ float gelu_exact(float x){
    return 0.5f * x * (1.0f + erff(x * 0.70710678118654752440f));
}
__device__ __forceinline__ float to_tf32(float x){
    uint32_t r;
    asm("cvt.rn.tf32.f32 %0, %1;" : "=r"(r) : "f"(x));
    return __uint_as_float(r);
}
__device__ __forceinline__ uint32_t s2u(const void* p){
    uint32_t a;
    asm("{ .reg .u64 t; cvta.to.shared.u64 t, %1; cvt.u32.u64 %0, t; }" : "=r"(a) : "l"(p));
    return a;
}
// K-permutation within each 8-group: (0,4,1,5,2,6,3,7) so (k, k+4) are adjacent
__device__ __forceinline__ int permk(int j){ return ((j&3)<<1) | (j>>2); }

#define CP_ASYNC16(dst, src) \
    asm volatile("cp.async.cg.shared.global [%0], [%1], 16;" :: "r"(dst), "l"(src))
#define CP_COMMIT() asm volatile("cp.async.commit_group;")
#define CP_WAIT(N)  asm volatile("cp.async.wait_group %0;" :: "n"(N) : "memory")

__device__ __forceinline__ void mma_tf32(float* d, const uint32_t* a, const uint32_t* b){
    asm volatile(
        "mma.sync.aligned.m16n8k8.row.col.f32.tf32.tf32.f32 "
        "{%0,%1,%2,%3}, {%4,%5,%6,%7}, {%8,%9}, {%0,%1,%2,%3};"
        : "+f"(d[0]), "+f"(d[1]), "+f"(d[2]), "+f"(d[3])
        : "r"(a[0]), "r"(a[1]), "r"(a[2]), "r"(a[3]), "r"(b[0]), "r"(b[1]));
}

// ---------------- elementwise kernels ------------------------------------------
__global__ void copy_kernel(float* __restrict__ dst, const float* __restrict__ src, int n){
    int i = blockIdx.x*blockDim.x + threadIdx.x;
    if(i < n) dst[i] = src[i];
}
// round to tf32 AND permute K within each 8-group (row length divisible by 8)
__global__ void round_perm(float* __restrict__ dst, const float* __restrict__ src, int n){
    int i = blockIdx.x*blockDim.x + threadIdx.x;
    if(i < n) dst[(i & ~7) | permk(i & 7)] = to_tf32(src[i]);
}
__global__ void concat_bias(const float* __restrict__ bq, const float* __restrict__ bk,
                            const float* __restrict__ bv, float* __restrict__ bqkv){
    int i = blockIdx.x*blockDim.x + threadIdx.x;   // over LAYERS*HH
    if(i < LAYERS*HH){
        int l = i / HH, c = i % HH;
        bqkv[(size_t)l*QKVS + c]        = bq[i];
        bqkv[(size_t)l*QKVS + KOFF + c] = bk[i];
        bqkv[(size_t)l*QKVS + VOFF + c] = bv[i];
    }
}

// transpose + round + permute: W [L][K][N] -> WT [L][rowOff+N][K] (K permuted)
__global__ void transpose_round(const float* __restrict__ W, float* __restrict__ WT,
                                int K, int N, size_t outLS, int rowOff){
    __shared__ float ts[32][33];
    const int l = blockIdx.z;
    const float* Wl = W + (size_t)l*K*N;
    float* WTl = WT + (size_t)l*outLS;
    const int n0 = blockIdx.x*32, k0 = blockIdx.y*32;
    const int tx = threadIdx.x, ty = threadIdx.y;  // 32 x 8
    #pragma unroll
    for(int i=0;i<4;i++)
        ts[ty+i*8][tx] = Wl[(size_t)(k0+ty+i*8)*N + n0 + tx];
    __syncthreads();
    const int pk = (tx & 24) | permk(tx & 7);
    #pragma unroll
    for(int i=0;i<4;i++)
        WTl[(size_t)(rowOff + n0+ty+i*8)*K + k0 + pk] = to_tf32(ts[tx][ty+i*8]);
}

// ---------------- TF32 tensor-core GEMM ----------------------------------------
// C[M,N] = A[M,K] @ WT[N,K]^T + bias. A and WT are K-permuted tf32 values.
// BN=128: 256 thr, 8 warps (4Mx2N, warp 32x64). BN=64: 128 thr, 4 warps (warp 32x64).
#define BK 32
#define PAD 40
#define GSTAGES 3
#define SM128 ((GSTAGES*(128+128)*PAD)*4)   // 122880
#define SM64  ((GSTAGES*(128+ 64)*PAD)*4)   // 92160

template<int BN, bool GELU, bool PERM>
__global__ __launch_bounds__(BN==128 ? 256 : 128)
void mma_gemm(const float* __restrict__ A, const float* __restrict__ Wt,
              const float* __restrict__ bias, float* __restrict__ C,
              int N, int K)
{
    constexpr int THREADS = (BN==128) ? 256 : 128;
    extern __shared__ float sm[];
    float* Asm = sm;                         // [GSTAGES][128][PAD]
    float* Wsm = sm + GSTAGES*128*PAD;       // [GSTAGES][BN][PAD]

    const int tid  = threadIdx.x;
    const int wid  = tid >> 5;
    const int lane = tid & 31;
    const int m0 = blockIdx.y * 128;
    const int n0 = blockIdx.x * BN;
    const int wm = (BN==128) ? (wid >> 1) * 32 : wid * 32;
    const int wn = (BN==128) ? (wid & 1) * 64 : 0;
    const int g  = lane >> 2;
    const int t4 = lane & 3;
    const int KT = K / BK;

    const float* Ag = A  + (size_t)m0 * K;
    const float* Wg = Wt + (size_t)n0 * K;

    auto load_tile = [&](int t){
        const int s = t % GSTAGES;
        float* as = Asm + s*128*PAD;
        float* ws = Wsm + s*BN*PAD;
        #pragma unroll
        for(int l=0;l<1024/THREADS;l++){
            const int c = tid + l*THREADS;
            const int row = c >> 3, k4 = c & 7;
            CP_ASYNC16(s2u(as + row*PAD + k4*4), Ag + (size_t)row*K + t*BK + k4*4);
        }
        #pragma unroll
        for(int l=0;l<(BN*8)/THREADS;l++){
            const int c = tid + l*THREADS;
            const int row = c >> 3, k4 = c & 7;
            CP_ASYNC16(s2u(ws + row*PAD + k4*4), Wg + (size_t)row*K + t*BK + k4*4);
        }
        CP_COMMIT();
    };

    float acc[2][8][4];
    #pragma unroll
    for(int mi=0;mi<2;mi++)
        #pragma unroll
        for(int ni=0;ni<8;ni++)
            #pragma unroll
            for(int r=0;r<4;r++) acc[mi][ni][r] = 0.f;

    load_tile(0);
    load_tile(1);

    for(int t=0; t<KT; t++){
        if (t < KT-1) CP_WAIT(1); else CP_WAIT(0);
        __syncthreads();

        const float* as = Asm + (t % GSTAGES)*128*PAD;
        const float* ws = Wsm + (t % GSTAGES)*BN*PAD;

        #pragma unroll
        for(int ks=0; ks<BK/8; ks++){
            uint32_t a[2][4], b[8][2];
            #pragma unroll
            for(int mi=0; mi<2; mi++){
                const float* ap = as + (wm + mi*16 + g)*PAD + ks*8 + 2*t4;
                float2 lo = *(const float2*)ap;            // (k=t4, k=t4+4) row g
                float2 hi = *(const float2*)(ap + 8*PAD);  // row g+8
                a[mi][0] = __float_as_uint(lo.x);
                a[mi][2] = __float_as_uint(lo.y);
                a[mi][1] = __float_as_uint(hi.x);
                a[mi][3] = __float_as_uint(hi.y);
            }
            #pragma unroll
            for(int ni=0; ni<8; ni++){
                const float* bp = ws + (wn + ni*8 + g)*PAD + ks*8 + 2*t4;
                float2 bv = *(const float2*)bp;
                b[ni][0] = __float_as_uint(bv.x);
                b[ni][1] = __float_as_uint(bv.y);
            }
            #pragma unroll
            for(int mi=0; mi<2; mi++)
                #pragma unroll
                for(int ni=0; ni<8; ni++)
                    mma_tf32(acc[mi][ni], a[mi], b[ni]);
        }
        __syncthreads();
        if (t+2 < KT) load_tile(t+2);
    }

    // epilogue
    #pragma unroll
    for(int mi=0; mi<2; mi++){
        #pragma unroll
        for(int ni=0; ni<8; ni++){
            const int r = m0 + wm + mi*16 + g;
            const int c = n0 + wn + ni*8 + 2*t4;
            const float bx = bias[c], by = bias[c+1];
            float v0 = acc[mi][ni][0] + bx;
            float v1 = acc[mi][ni][1] + by;
            float v2 = acc[mi][ni][2] + bx;
            float v3 = acc[mi][ni][3] + by;
            if (GELU){
                v0 = gelu_exact(v0); v1 = gelu_exact(v1);
                v2 = gelu_exact(v2); v3 = gelu_exact(v3);
            }
            if (PERM){
                // round to tf32 and store K-permuted (output feeds another GEMM as A)
                const int base8 = c & ~7;
                const int p0 = base8 + permk(2*t4);
                const int p1 = base8 + permk(2*t4 + 1);
                C[(size_t)r*N + p0]     = to_tf32(v0);
                C[(size_t)r*N + p1]     = to_tf32(v1);
                C[(size_t)(r+8)*N + p0] = to_tf32(v2);
                C[(size_t)(r+8)*N + p1] = to_tf32(v3);
            } else {
                *(float2*)(C + (size_t)r*N + c)     = make_float2(v0, v1);
                *(float2*)(C + (size_t)(r+8)*N + c) = make_float2(v2, v3);
            }
        }
    }
}

// ---------------- attention scores: S = Q K^T / 8 + mask ------------------------
__global__ __launch_bounds__(256)
void attn_scores(const float* __restrict__ qkv, const float* __restrict__ mask,
                 float* __restrict__ scores)
{
    __shared__ float Qst[64][68];
    __shared__ float Kst[64][68];

    const int bh   = blockIdx.z;
    const int b    = bh / NHD;
    const int head = bh % NHD;
    const int q0   = blockIdx.y * 64;
    const int n0   = blockIdx.x * 64;
    const int tid  = threadIdx.x;
    const int tx   = tid & 15;
    const int ty   = tid >> 4;

    const float* Qb = qkv + (size_t)(b*SS + q0)*QKVS + head*DHD;
    const float* Kb = qkv + (size_t)(b*SS + n0)*QKVS + KOFF + head*DHD;

    #pragma unroll
    for(int l=0;l<4;l++){
        int f   = tid + l*256;
        int row = f >> 4;
        int c4  = f & 15;
        float4 vq = *(const float4*)(Qb + (size_t)row*QKVS + c4*4);
        float4 vk = *(const float4*)(Kb + (size_t)row*QKVS + c4*4);
        Qst[c4*4+0][row]=vq.x; Qst[c4*4+1][row]=vq.y;
        Qst[c4*4+2][row]=vq.z; Qst[c4*4+3][row]=vq.w;
        Kst[c4*4+0][row]=vk.x; Kst[c4*4+1][row]=vk.y;
        Kst[c4*4+2][row]=vk.z; Kst[c4*4+3][row]=vk.w;
    }
    __syncthreads();

    float acc[4][4];
    #pragma unroll
    for(int i=0;i<4;i++)
        #pragma unroll
        for(int j=0;j<4;j++) acc[i][j]=0.f;

    #pragma unroll 4
    for(int k=0;k<64;k++){
        float a[4], bb2[4];
        *(float4*)a   = *(const float4*)(&Qst[k][ty*4]);
        *(float4*)bb2 = *(const float4*)(&Kst[k][tx*4]);
        #pragma unroll
        for(int i=0;i<4;i++)
            #pragma unroll
            for(int j=0;j<4;j++)
                acc[i][j] = fmaf(a[i], bb2[j], acc[i][j]);
    }

    float4 mv = *(const float4*)(mask + b*SS + n0 + tx*4);
    #pragma unroll
    for(int i=0;i<4;i++){
        float4 r;
        r.x = acc[i][0]*0.125f + mv.x;
        r.y = acc[i][1]*0.125f + mv.y;
        r.z = acc[i][2]*0.125f + mv.z;
        r.w = acc[i][3]*0.125f + mv.w;
        *(float4*)(scores + ((size_t)bh*SS + q0 + ty*4 + i)*SS + n0 + tx*4) = r;
    }
}

// ---------------- softmax over rows of 512 --------------------------------------
__global__ __launch_bounds__(128)
void softmax_rows(float* __restrict__ scores)
{
    float* p = scores + (size_t)blockIdx.x * SS;
    const int t = threadIdx.x;
    float v[4];
    float mx = -1e30f;
    #pragma unroll
    for(int i=0;i<4;i++){ v[i] = p[t + i*128]; mx = fmaxf(mx, v[i]); }

    __shared__ float sm[4];
    float wmx = warpMax(mx);
    int warp = t >> 5, lane = t & 31;
    if(lane==0) sm[warp] = wmx;
    __syncthreads();
    float bm = fmaxf(fmaxf(sm[0],sm[1]), fmaxf(sm[2],sm[3]));

    float s = 0.f;
    #pragma unroll
    for(int i=0;i<4;i++){ v[i] = __expf(v[i] - bm); s += v[i]; }
    float ws = warpSum(s);
    __syncthreads();
    if(lane==0) sm[warp] = ws;
    __syncthreads();
    float tot = sm[0]+sm[1]+sm[2]+sm[3];
    float inv = 1.0f / tot;
    #pragma unroll
    for(int i=0;i<4;i++) p[t + i*128] = v[i] * inv;
}

// ---------------- ctx = P @ V  (tf32-rounded, K-permuted store) -------------------
__global__ __launch_bounds__(256)
void attn_ctx(const float* __restrict__ P, const float* __restrict__ qkv,
              float* __restrict__ ctx)
{
    __shared__ float Ps[64][36];
    __shared__ float Vs[32][64];

    const int bh   = blockIdx.y;
    const int b    = bh / NHD;
    const int head = bh % NHD;
    const int q0   = blockIdx.x * 64;
    const int tid  = threadIdx.x;
    const int tx   = tid & 15;
    const int ty   = tid >> 4;

    const float* Pb = P + ((size_t)bh*SS + q0) * SS;
    const float* Vb = qkv + (size_t)(b*SS)*QKVS + VOFF + head*DHD;

    float acc[4][4];
    #pragma unroll
    for(int i=0;i<4;i++)
        #pragma unroll
        for(int j=0;j<4;j++) acc[i][j]=0.f;

    for(int kt=0; kt<SS; kt+=32){
        #pragma unroll
        for(int l=0;l<2;l++){
            int f   = tid + l*256;
            int row = f >> 3;
            int c4  = f & 7;
            *(float4*)(&Ps[row][c4*4]) =
                *(const float4*)(Pb + (size_t)row*SS + kt + c4*4);
        }
        #pragma unroll
        for(int l=0;l<2;l++){
            int f   = tid + l*256;
            int row = f >> 4;
            int c4  = f & 15;
            *(float4*)(&Vs[row][c4*4]) =
                *(const float4*)(Vb + (size_t)(kt+row)*QKVS + c4*4);
        }
        __syncthreads();

        #pragma unroll 4
        for(int k=0;k<32;k++){
            float bb2[4];
            *(float4*)bb2 = *(const float4*)(&Vs[k][tx*4]);
            float a0 = Ps[ty*4+0][k];
            float a1 = Ps[ty*4+1][k];
            float a2 = Ps[ty*4+2][k];
            float a3 = Ps[ty*4+3][k];
            #pragma unroll
            for(int j=0;j<4;j++){
                acc[0][j] = fmaf(a0, bb2[j], acc[0][j]);
                acc[1][j] = fmaf(a1, bb2[j], acc[1][j]);
                acc[2][j] = fmaf(a2, bb2[j], acc[2][j]);
                acc[3][j] = fmaf(a3, bb2[j], acc[3][j]);
            }
        }
        __syncthreads();
    }

    // store K-permuted (ctx feeds the Wo GEMM as A)
    const int cc = tx*4;
    const int base8 = cc & ~7;
    const int j0 = cc & 7;
    #pragma unroll
    for(int i=0;i<4;i++){
        float* op = ctx + (size_t)(b*SS + q0 + ty*4 + i)*HH + head*DHD;
        #pragma unroll
        for(int jj=0;jj<4;jj++)
            op[base8 + permk(j0 + jj)] = to_tf32(acc[i][jj]);
    }
}

// ---------------- add residual + layernorm ---------------------------------------
__global__ __launch_bounds__(256)
void add_layernorm(const float* __restrict__ x, const float* __restrict__ res,
                   const float* __restrict__ g, const float* __restrict__ bta,
                   float* __restrict__ out)
{
    const int tok = blockIdx.x;
    const float* xp = x   + (size_t)tok*HH;
    const float* rp = res + (size_t)tok*HH;
    float* op       = out + (size_t)tok*HH;
    const int t = threadIdx.x;

    float v[3];
    float s = 0.f, sq = 0.f;
    #pragma unroll
    for(int i=0;i<3;i++){
        int c = t + i*256;
        float val = xp[c] + rp[c];
        v[i] = val; s += val; sq += val*val;
    }

    __shared__ float rs[8], rq[8];
    float ws = warpSum(s), wq = warpSum(sq);
    int warp = t >> 5, lane = t & 31;
    if(lane==0){ rs[warp]=ws; rq[warp]=wq; }
    __syncthreads();
    if(warp==0){
        float a = (lane<8)? rs[lane] : 0.f;
        float bq2 = (lane<8)? rq[lane] : 0.f;
        a = warpSum(a); bq2 = warpSum(bq2);
        if(lane==0){ rs[0]=a; rq[0]=bq2; }
    }
    __syncthreads();
    const float mean = rs[0] * (1.0f/768.0f);
    const float var  = rq[0] * (1.0f/768.0f) - mean*mean;
    const float inv  = rsqrtf(var + 1e-12f);

    #pragma unroll
    for(int i=0;i<3;i++){
        int c = t + i*256;
        op[c] = (v[i] - mean) * inv * g[c] + bta[c];
    }
}

// ---------------- launch -----------------------------------------------------------
extern "C" void kernel_launch(void* const* d_in, const int* in_sizes, int n_in,
                              void* d_out, int out_size)
{
    const float* hs   = (const float*)d_in[0];
    const float* mask = (const float*)d_in[1];
    const float* Wq   = (const float*)d_in[2];
    const float* bq   = (const float*)d_in[3];
    const float* Wk   = (const float*)d_in[4];
    const float* bk   = (const float*)d_in[5];
    const float* Wv   = (const float*)d_in[6];
    const float* bv   = (const float*)d_in[7];
    const float* Wo   = (const float*)d_in[8];
    const float* bo   = (const float*)d_in[9];
    const float* g1   = (const float*)d_in[10];
    const float* b1   = (const float*)d_in[11];
    const float* Wi   = (const float*)d_in[12];
    const float* bi   = (const float*)d_in[13];
    const float* Wo2  = (const float*)d_in[14];
    const float* bo2  = (const float*)d_in[15];
    const float* g2   = (const float*)d_in[16];
    const float* b2   = (const float*)d_in[17];

    float *h, *qkv, *ctx, *attn, *tmp, *inter, *scores, *rA;
    float *wqkvT, *bqkv, *woT, *wiT, *wo2T;
    cudaGetSymbolAddress((void**)&h,      g_h);
    cudaGetSymbolAddress((void**)&qkv,    g_qkv);
    cudaGetSymbolAddress((void**)&ctx,    g_ctx);
    cudaGetSymbolAddress((void**)&attn,   g_attn);
    cudaGetSymbolAddress((void**)&tmp,    g_tmp);
    cudaGetSymbolAddress((void**)&inter,  g_inter);
    cudaGetSymbolAddress((void**)&scores, g_scores);
    cudaGetSymbolAddress((void**)&rA,     g_round);
    cudaGetSymbolAddress((void**)&wqkvT,  g_wqkvT);
    cudaGetSymbolAddress((void**)&bqkv,   g_bqkv);
    cudaGetSymbolAddress((void**)&woT,    g_woT);
    cudaGetSymbolAddress((void**)&wiT,    g_wiT);
    cudaGetSymbolAddress((void**)&wo2T,   g_wo2T);

    cudaFuncSetAttribute(mma_gemm<128,false,false>, cudaFuncAttributeMaxDynamicSharedMemorySize, SM128);
    cudaFuncSetAttribute(mma_gemm<128,true, true >, cudaFuncAttributeMaxDynamicSharedMemorySize, SM128);
    cudaFuncSetAttribute(mma_gemm<64, false,false>, cudaFuncAttributeMaxDynamicSharedMemorySize, SM64);

    // weight prep: transpose + tf32 round + K-permute
    transpose_round<<<dim3(HH/32,  HH/32,  LAYERS), dim3(32,8)>>>(Wq,  wqkvT, HH,  HH,  (size_t)QKVS*HH, 0);
    transpose_round<<<dim3(HH/32,  HH/32,  LAYERS), dim3(32,8)>>>(Wk,  wqkvT, HH,  HH,  (size_t)QKVS*HH, KOFF);
    transpose_round<<<dim3(HH/32,  HH/32,  LAYERS), dim3(32,8)>>>(Wv,  wqkvT, HH,  HH,  (size_t)QKVS*HH, VOFF);
    transpose_round<<<dim3(HH/32,  HH/32,  LAYERS), dim3(32,8)>>>(Wo,  woT,   HH,  HH,  (size_t)HH*HH,   0);
    transpose_round<<<dim3(FFD/32, HH/32,  LAYERS), dim3(32,8)>>>(Wi,  wiT,   HH,  FFD, (size_t)HH*FFD,  0);
    transpose_round<<<dim3(HH/32,  FFD/32, LAYERS), dim3(32,8)>>>(Wo2, wo2T,  FFD, HH,  (size_t)FFD*HH,  0);
    concat_bias<<<(LAYERS*HH+255)/256, 256>>>(bq, bk, bv, bqkv);

    const int nH = M_TOK*HH;
    copy_kernel<<<(nH+255)/256, 256>>>(h, hs, nH);

    dim3 gQKV(QKVS/128, M_TOK/128);   // (18, 32)
    dim3 gFF1(FFD/128,  M_TOK/128);   // (24, 32)
    dim3 gN64(HH/64,    M_TOK/128);   // (12, 32)

    for(int l=0; l<LAYERS; l++){
        const float* lbo  = bo  + (size_t)l*HH;
        const float* lbi  = bi  + (size_t)l*FFD;
        const float* lbo2 = bo2 + (size_t)l*HH;
        const float* lg1  = g1  + (size_t)l*HH;
        const float* lb1  = b1  + (size_t)l*HH;
        const float* lg2  = g2  + (size_t)l*HH;
        const float* lb2  = b2  + (size_t)l*HH;

        round_perm<<<(nH+255)/256, 256>>>(rA, h, nH);
        mma_gemm<128,false,false><<<gQKV, 256, SM128>>>(
            rA, wqkvT + (size_t)l*QKVS*HH, bqkv + (size_t)l*QKVS, qkv, QKVS, HH);

        attn_scores<<<dim3(8,8,BB*NHD), 256>>>(qkv, mask, scores);
        softmax_rows<<<BB*NHD*SS, 128>>>(scores);
        attn_ctx<<<dim3(8,BB*NHD), 256>>>(scores, qkv, ctx);

        mma_gemm<64,false,false><<<gN64, 128, SM64>>>(
            ctx, woT + (size_t)l*HH*HH, lbo, tmp, HH, HH);
        add_layernorm<<<M_TOK, 256>>>(tmp, h, lg1, lb1, attn);

        round_perm<<<(nH+255)/256, 256>>>(rA, attn, nH);
        mma_gemm<128,true,true><<<gFF1, 256, SM128>>>(
            rA, wiT + (size_t)l*HH*FFD, lbi, inter, FFD, HH);
        mma_gemm<64,false,false><<<gN64, 128, SM64>>>(
            inter, wo2T + (size_t)l*FFD*HH, lbo2, tmp, HH, FFD);
        add_layernorm<<<M_TOK, 256>>>(tmp, attn, lg2, lb2,
                                      (l==LAYERS-1) ? (float*)d_out : h);
    }
}

// round 5
// speedup vs baseline: 2.8263x; 1.3219x over previous
#include <cuda_runtime.h>
#include <math.h>
#include <stdint.h>

#define LAYERS 12
#define BB 8
#define SS 512
#define HH 768
#define NHD 12
#define DHD 64
#define FFD 3072
#define M_TOK (BB*SS)   // 4096
#define QKVS 2304
#define KOFF 768
#define VOFF 1536

// ---------------- scratch -----------------------------------------------------
__device__ float g_h[M_TOK*HH];
__device__ float g_qkv[M_TOK*QKVS];
__device__ float g_vT[BB*NHD*DHD*SS];      // [bh*64+d][s]
__device__ float g_ctx[M_TOK*HH];
__device__ float g_attn[M_TOK*HH];
__device__ float g_tmp[M_TOK*HH];
__device__ float g_round[M_TOK*HH];
__device__ float g_inter[M_TOK*FFD];

__device__ float g_wqkvT[LAYERS*QKVS*HH];
__device__ float g_bqkv [LAYERS*QKVS];
__device__ float g_woT  [LAYERS*HH*HH];
__device__ float g_wiT  [LAYERS*HH*FFD];
__device__ float g_wo2T [LAYERS*FFD*HH];

// ---------------- helpers -----------------------------------------------------
__inline__ __device__ float warpSum(float v){
    #pragma unroll
    for(int o=16;o;o>>=1) v += __shfl_xor_sync(0xffffffffu, v, o);
    return v;
}
__device__ __forceinline__ float gelu_exact(float x){
    return 0.5f * x * (1.0f + erff(x * 0.70710678118654752440f));
}
__device__ __forceinline__ float to_tf32(float x){
    uint32_t r;
    asm("cvt.rn.tf32.f32 %0, %1;" : "=r"(r) : "f"(x));
    return __uint_as_float(r);
}
__device__ __forceinline__ uint32_t s2u(const void* p){
    uint32_t a;
    asm("{ .reg .u64 t; cvta.to.shared.u64 t, %1; cvt.u32.u64 %0, t; }" : "=r"(a) : "l"(p));
    return a;
}
__device__ __forceinline__ int permk(int j){ return ((j&3)<<1) | (j>>2); }

// exp(x) for x <= 0 on the FMA/ALU pipes (no MUFU). rel err ~3e-6.
__device__ __forceinline__ float exp_fma(float x){
    x = fmaxf(x, -80.0f);
    float y  = x * 1.44269504088896341f;
    float nm = y + 12582912.0f;          // round-to-nearest int (magic)
    float n  = nm - 12582912.0f;
    float f  = y - n;
    float p  = 1.3333558146428443e-3f;
    p = fmaf(p, f, 9.6181291851826464e-3f);
    p = fmaf(p, f, 5.5504108664821580e-2f);
    p = fmaf(p, f, 2.4022650695910071e-1f);
    p = fmaf(p, f, 6.9314718055994531e-1f);
    p = fmaf(p, f, 1.0f);
    int e = __float_as_int(nm) + (127 - 0x4B400000);
    return p * __int_as_float(e << 23);
}

#define CP_ASYNC16(dst, src) \
    asm volatile("cp.async.cg.shared.global [%0], [%1], 16;" :: "r"(dst), "l"(src))
#define CP_COMMIT() asm volatile("cp.async.commit_group;")
#define CP_WAIT(N)  asm volatile("cp.async.wait_group %0;" :: "n"(N) : "memory")

__device__ __forceinline__ void mma_tf32(float* d, const uint32_t* a, const uint32_t* b){
    asm volatile(
        "mma.sync.aligned.m16n8k8.row.col.f32.tf32.tf32.f32 "
        "{%0,%1,%2,%3}, {%4,%5,%6,%7}, {%8,%9}, {%0,%1,%2,%3};"
        : "+f"(d[0]), "+f"(d[1]), "+f"(d[2]), "+f"(d[3])
        : "r"(a[0]), "r"(a[1]), "r"(a[2]), "r"(a[3]), "r"(b[0]), "r"(b[1]));
}

// ---------------- elementwise ---------------------------------------------------
__global__ void copy_kernel(float* __restrict__ dst, const float* __restrict__ src, int n){
    int i = blockIdx.x*blockDim.x + threadIdx.x;
    if(i < n) dst[i] = src[i];
}
__global__ void round_perm(float* __restrict__ dst, const float* __restrict__ src, int n){
    int i = blockIdx.x*blockDim.x + threadIdx.x;
    if(i < n) dst[(i & ~7) | permk(i & 7)] = to_tf32(src[i]);
}
__global__ void concat_bias(const float* __restrict__ bq, const float* __restrict__ bk,
                            const float* __restrict__ bv, float* __restrict__ bqkv){
    int i = blockIdx.x*blockDim.x + threadIdx.x;
    if(i < LAYERS*HH){
        int l = i / HH, c = i % HH;
        bqkv[(size_t)l*QKVS + c]        = bq[i];
        bqkv[(size_t)l*QKVS + KOFF + c] = bk[i];
        bqkv[(size_t)l*QKVS + VOFF + c] = bv[i];
    }
}
__global__ void transpose_round(const float* __restrict__ W, float* __restrict__ WT,
                                int K, int N, size_t outLS, int rowOff){
    __shared__ float ts[32][33];
    const int l = blockIdx.z;
    const float* Wl = W + (size_t)l*K*N;
    float* WTl = WT + (size_t)l*outLS;
    const int n0 = blockIdx.x*32, k0 = blockIdx.y*32;
    const int tx = threadIdx.x, ty = threadIdx.y;
    #pragma unroll
    for(int i=0;i<4;i++)
        ts[ty+i*8][tx] = Wl[(size_t)(k0+ty+i*8)*N + n0 + tx];
    __syncthreads();
    const int pk = (tx & 24) | permk(tx & 7);
    #pragma unroll
    for(int i=0;i<4;i++)
        WTl[(size_t)(rowOff + n0+ty+i*8)*K + k0 + pk] = to_tf32(ts[tx][ty+i*8]);
}

// ---------------- TF32 GEMM -----------------------------------------------------
// MODE 0: plain +bias. MODE 1: gelu + tf32-round + K-perm store. MODE 2: QKV
// (Q: x0.125 + round + perm; K: round + perm; V: round + transpose into vT).
#define BK 32
#define PAD 40
#define GSTAGES 3
#define SM128 ((GSTAGES*(128+128)*PAD)*4)
#define SM64  ((GSTAGES*(128+ 64)*PAD)*4)

template<int BN, int MODE>
__global__ __launch_bounds__(BN==128 ? 256 : 128)
void mma_gemm(const float* __restrict__ A, const float* __restrict__ Wt,
              const float* __restrict__ bias, float* __restrict__ C,
              float* __restrict__ vT, int N, int K)
{
    constexpr int THREADS = (BN==128) ? 256 : 128;
    extern __shared__ float sm[];
    float* Asm = sm;
    float* Wsm = sm + GSTAGES*128*PAD;

    const int tid  = threadIdx.x;
    const int wid  = tid >> 5;
    const int lane = tid & 31;
    const int m0 = blockIdx.y * 128;
    const int n0 = blockIdx.x * BN;
    const int wm = (BN==128) ? (wid >> 1) * 32 : wid * 32;
    const int wn = (BN==128) ? (wid & 1) * 64 : 0;
    const int g  = lane >> 2;
    const int t4 = lane & 3;
    const int KT = K / BK;

    const float* Ag = A  + (size_t)m0 * K;
    const float* Wg = Wt + (size_t)n0 * K;

    auto load_tile = [&](int t){
        const int s = t % GSTAGES;
        float* as = Asm + s*128*PAD;
        float* ws = Wsm + s*BN*PAD;
        #pragma unroll
        for(int l=0;l<1024/THREADS;l++){
            const int c = tid + l*THREADS;
            const int row = c >> 3, k4 = c & 7;
            CP_ASYNC16(s2u(as + row*PAD + k4*4), Ag + (size_t)row*K + t*BK + k4*4);
        }
        #pragma unroll
        for(int l=0;l<(BN*8)/THREADS;l++){
            const int c = tid + l*THREADS;
            const int row = c >> 3, k4 = c & 7;
            CP_ASYNC16(s2u(ws + row*PAD + k4*4), Wg + (size_t)row*K + t*BK + k4*4);
        }
        CP_COMMIT();
    };

    float acc[2][8][4];
    #pragma unroll
    for(int mi=0;mi<2;mi++)
        #pragma unroll
        for(int ni=0;ni<8;ni++)
            #pragma unroll
            for(int r=0;r<4;r++) acc[mi][ni][r] = 0.f;

    load_tile(0);
    load_tile(1);

    for(int t=0; t<KT; t++){
        if (t < KT-1) CP_WAIT(1); else CP_WAIT(0);
        __syncthreads();

        const float* as = Asm + (t % GSTAGES)*128*PAD;
        const float* ws = Wsm + (t % GSTAGES)*BN*PAD;

        #pragma unroll
        for(int ks=0; ks<BK/8; ks++){
            uint32_t a[2][4], b[8][2];
            #pragma unroll
            for(int mi=0; mi<2; mi++){
                const float* ap = as + (wm + mi*16 + g)*PAD + ks*8 + 2*t4;
                float2 lo = *(const float2*)ap;
                float2 hi = *(const float2*)(ap + 8*PAD);
                a[mi][0] = __float_as_uint(lo.x);
                a[mi][2] = __float_as_uint(lo.y);
                a[mi][1] = __float_as_uint(hi.x);
                a[mi][3] = __float_as_uint(hi.y);
            }
            #pragma unroll
            for(int ni=0; ni<8; ni++){
                const float* bp = ws + (wn + ni*8 + g)*PAD + ks*8 + 2*t4;
                float2 bv = *(const float2*)bp;
                b[ni][0] = __float_as_uint(bv.x);
                b[ni][1] = __float_as_uint(bv.y);
            }
            #pragma unroll
            for(int mi=0; mi<2; mi++)
                #pragma unroll
                for(int ni=0; ni<8; ni++)
                    mma_tf32(acc[mi][ni], a[mi], b[ni]);
        }
        __syncthreads();
        if (t+2 < KT) load_tile(t+2);
    }

    if (MODE == 2 && n0 >= VOFF){
        // V: round + transpose into vT[(b*768 + c-1536)][s]
        __syncthreads();
        float* stage = sm + wid*2304;   // [64 d][36]
        #pragma unroll
        for(int mi=0; mi<2; mi++){
            #pragma unroll
            for(int ni=0; ni<8; ni++){
                const int cl = ni*8 + 2*t4;
                const int sl = mi*16 + g;
                const float b0 = bias[n0+wn+cl], b1 = bias[n0+wn+cl+1];
                stage[(cl  )*36 + sl  ] = to_tf32(acc[mi][ni][0] + b0);
                stage[(cl+1)*36 + sl  ] = to_tf32(acc[mi][ni][1] + b1);
                stage[(cl  )*36 + sl+8] = to_tf32(acc[mi][ni][2] + b0);
                stage[(cl+1)*36 + sl+8] = to_tf32(acc[mi][ni][3] + b1);
            }
        }
        __syncwarp();
        const int b    = m0 >> 9;
        const int soff = (m0 + wm) & 511;
        #pragma unroll
        for(int t=0; t<16; t++){
            const int chunk = lane + t*32;
            const int dr = chunk >> 3, c4 = chunk & 7;
            float4 val = *(const float4*)(stage + dr*36 + c4*4);
            *(float4*)(vT + ((size_t)(b*768 + (n0 - VOFF) + wn + dr))*512 + soff + c4*4) = val;
        }
        return;
    }

    #pragma unroll
    for(int mi=0; mi<2; mi++){
        #pragma unroll
        for(int ni=0; ni<8; ni++){
            const int r = m0 + wm + mi*16 + g;
            const int c = n0 + wn + ni*8 + 2*t4;
            const float bx = bias[c], by = bias[c+1];
            float v0 = acc[mi][ni][0] + bx;
            float v1 = acc[mi][ni][1] + by;
            float v2 = acc[mi][ni][2] + bx;
            float v3 = acc[mi][ni][3] + by;
            if (MODE == 1){
                v0 = gelu_exact(v0); v1 = gelu_exact(v1);
                v2 = gelu_exact(v2); v3 = gelu_exact(v3);
            }
            if (MODE == 2){
                const float sc = (n0 < KOFF) ? 0.125f : 1.0f;
                v0 *= sc; v1 *= sc; v2 *= sc; v3 *= sc;
            }
            if (MODE == 1 || MODE == 2){
                const int base8 = c & ~7;
                const int p0 = base8 + permk(2*t4);
                const int p1 = base8 + permk(2*t4 + 1);
                C[(size_t)r*N + p0]     = to_tf32(v0);
                C[(size_t)r*N + p1]     = to_tf32(v1);
                C[(size_t)(r+8)*N + p0] = to_tf32(v2);
                C[(size_t)(r+8)*N + p1] = to_tf32(v3);
            } else {
                *(float2*)(C + (size_t)r*N + c)     = make_float2(v0, v1);
                *(float2*)(C + (size_t)(r+8)*N + c) = make_float2(v2, v3);
            }
        }
    }
}

// ---------------- fused flash attention (tf32 mma) -------------------------------
// grid (4 qtiles, 96 bh), 256 threads (8 warps, warp = 16 q-rows).
#define FL_SMEM 112640

__global__ __launch_bounds__(256, 2)
void flash_attn(const float* __restrict__ qkv, const float* __restrict__ vT,
                const float* __restrict__ mask, float* __restrict__ ctx)
{
    extern __shared__ float fs[];
    float* Qs  = fs;              // [128][72]
    float* Ksm = fs + 9216;       // [2][64][72]
    float* Vsm = fs + 18432;      // [2][64][72]
    float* msk = fs + 27648;      // [512]

    const int tid  = threadIdx.x;
    const int wid  = tid >> 5;
    const int lane = tid & 31;
    const int g  = lane >> 2;
    const int t4 = lane & 3;
    const int qt = blockIdx.x;
    const int bh = blockIdx.y;
    const int b    = bh / NHD;
    const int head = bh % NHD;

    const float* Qg = qkv + ((size_t)(b*SS + qt*128))*QKVS + head*DHD;
    const float* Kg = qkv + ((size_t)(b*SS))*QKVS + KOFF + head*DHD;
    const float* Vg = vT  + ((size_t)(b*HH + head*DHD))*SS;

    if (tid < 128)
        *(float4*)(msk + tid*4) = *(const float4*)(mask + b*SS + tid*4);

    // Q tile (once)
    #pragma unroll
    for(int i=0;i<8;i++){
        const int c = tid + i*256;
        const int row = c >> 4, c4 = c & 15;
        CP_ASYNC16(s2u(Qs + row*72 + c4*4), Qg + (size_t)row*QKVS + c4*4);
    }
    CP_COMMIT();

    auto load_kv = [&](int kt){
        float* ks = Ksm + (kt&1)*4608;
        float* vs = Vsm + (kt&1)*4608;
        #pragma unroll
        for(int i=0;i<4;i++){
            const int c = tid + i*256;
            const int row = c >> 4, c4 = c & 15;
            CP_ASYNC16(s2u(ks + row*72 + c4*4), Kg + (size_t)(kt*64+row)*QKVS + c4*4);
            CP_ASYNC16(s2u(vs + row*72 + c4*4), Vg + (size_t)row*SS + kt*64 + c4*4);
        }
        CP_COMMIT();
    };
    load_kv(0);
    load_kv(1);

    float ctxa[8][4];
    #pragma unroll
    for(int dt=0;dt<8;dt++)
        #pragma unroll
        for(int r=0;r<4;r++) ctxa[dt][r]=0.f;
    float m0=-1e30f, m1=-1e30f, l0=0.f, l1=0.f;

    const float* qb = Qs + (wid*16 + g)*72 + 2*t4;

    for(int kt=0; kt<8; kt++){
        if (kt < 7) CP_WAIT(1); else CP_WAIT(0);
        __syncthreads();

        const float* ks = Ksm + (kt&1)*4608;
        const float* vs = Vsm + (kt&1)*4608;

        float sacc[8][4];
        #pragma unroll
        for(int nt=0;nt<8;nt++)
            #pragma unroll
            for(int r=0;r<4;r++) sacc[nt][r]=0.f;

        #pragma unroll
        for(int ksi=0; ksi<8; ksi++){
            uint32_t a[4];
            float2 qlo = *(const float2*)(qb + ksi*8);
            float2 qhi = *(const float2*)(qb + 8*72 + ksi*8);
            a[0] = __float_as_uint(qlo.x);
            a[1] = __float_as_uint(qhi.x);
            a[2] = __float_as_uint(qlo.y);
            a[3] = __float_as_uint(qhi.y);
            #pragma unroll
            for(int nt=0; nt<8; nt++){
                float2 bv = *(const float2*)(ks + (nt*8+g)*72 + ksi*8 + 2*t4);
                uint32_t br[2] = { __float_as_uint(bv.x), __float_as_uint(bv.y) };
                mma_tf32(sacc[nt], a, br);
            }
        }

        // mask + row max
        float r0 = -1e30f, r1 = -1e30f;
        #pragma unroll
        for(int nt=0; nt<8; nt++){
            const float mk0 = msk[kt*64 + nt*8 + 2*t4];
            const float mk1 = msk[kt*64 + nt*8 + 2*t4 + 1];
            sacc[nt][0] += mk0; sacc[nt][1] += mk1;
            sacc[nt][2] += mk0; sacc[nt][3] += mk1;
            r0 = fmaxf(r0, fmaxf(sacc[nt][0], sacc[nt][1]));
            r1 = fmaxf(r1, fmaxf(sacc[nt][2], sacc[nt][3]));
        }
        r0 = fmaxf(r0, __shfl_xor_sync(0xffffffffu, r0, 1));
        r0 = fmaxf(r0, __shfl_xor_sync(0xffffffffu, r0, 2));
        r1 = fmaxf(r1, __shfl_xor_sync(0xffffffffu, r1, 1));
        r1 = fmaxf(r1, __shfl_xor_sync(0xffffffffu, r1, 2));

        const float mn0 = fmaxf(m0, r0);
        const float mn1 = fmaxf(m1, r1);
        const float al0 = exp_fma(m0 - mn0);
        const float al1 = exp_fma(m1 - mn1);
        m0 = mn0; m1 = mn1;
        l0 *= al0; l1 *= al1;
        #pragma unroll
        for(int dt=0; dt<8; dt++){
            ctxa[dt][0] *= al0; ctxa[dt][1] *= al0;
            ctxa[dt][2] *= al1; ctxa[dt][3] *= al1;
        }

        float ps0 = 0.f, ps1 = 0.f;
        #pragma unroll
        for(int nt=0; nt<8; nt++){
            sacc[nt][0] = to_tf32(exp_fma(sacc[nt][0]-mn0)); ps0 += sacc[nt][0];
            sacc[nt][1] = to_tf32(exp_fma(sacc[nt][1]-mn0)); ps0 += sacc[nt][1];
            sacc[nt][2] = to_tf32(exp_fma(sacc[nt][2]-mn1)); ps1 += sacc[nt][2];
            sacc[nt][3] = to_tf32(exp_fma(sacc[nt][3]-mn1)); ps1 += sacc[nt][3];
        }
        l0 += ps0; l1 += ps1;

        // PV: a-frag comes straight from p registers
        #pragma unroll
        for(int dt=0; dt<8; dt++){
            #pragma unroll
            for(int ksi=0; ksi<8; ksi++){
                float2 bv = *(const float2*)(vs + (dt*8+g)*72 + ksi*8 + 2*t4);
                uint32_t br[2] = { __float_as_uint(bv.x), __float_as_uint(bv.y) };
                uint32_t a[4] = { __float_as_uint(sacc[ksi][0]),
                                  __float_as_uint(sacc[ksi][2]),
                                  __float_as_uint(sacc[ksi][1]),
                                  __float_as_uint(sacc[ksi][3]) };
                mma_tf32(ctxa[dt], a, br);
            }
        }
        __syncthreads();
        if (kt + 2 < 8) load_kv(kt + 2);
    }

    l0 += __shfl_xor_sync(0xffffffffu, l0, 1);
    l0 += __shfl_xor_sync(0xffffffffu, l0, 2);
    l1 += __shfl_xor_sync(0xffffffffu, l1, 1);
    l1 += __shfl_xor_sync(0xffffffffu, l1, 2);
    const float inv0 = 1.0f / l0;
    const float inv1 = 1.0f / l1;

    const int token0 = b*SS + qt*128 + wid*16 + g;
    float* o0 = ctx + (size_t)token0*HH + head*DHD;
    float* o1 = o0 + (size_t)8*HH;
    #pragma unroll
    for(int dt=0; dt<8; dt++){
        const int p0 = dt*8 + permk(2*t4);
        const int p1 = dt*8 + permk(2*t4 + 1);
        o0[p0] = to_tf32(ctxa[dt][0] * inv0);
        o0[p1] = to_tf32(ctxa[dt][1] * inv0);
        o1[p0] = to_tf32(ctxa[dt][2] * inv1);
        o1[p1] = to_tf32(ctxa[dt][3] * inv1);
    }
}

// ---------------- add residual + layernorm (dual output) --------------------------
__global__ __launch_bounds__(256)
void add_layernorm_dual(const float* __restrict__ x, const float* __restrict__ res,
                        const float* __restrict__ g, const float* __restrict__ bta,
                        float* __restrict__ out, float* __restrict__ outp)
{
    const int tok = blockIdx.x;
    const float* xp = x   + (size_t)tok*HH;
    const float* rp = res + (size_t)tok*HH;
    float* op  = out  + (size_t)tok*HH;
    float* opp = outp + (size_t)tok*HH;
    const int t = threadIdx.x;

    float v[3];
    float s = 0.f, sq = 0.f;
    #pragma unroll
    for(int i=0;i<3;i++){
        int c = t + i*256;
        float val = xp[c] + rp[c];
        v[i] = val; s += val; sq += val*val;
    }

    __shared__ float rs[8], rq[8];
    float ws = warpSum(s), wq = warpSum(sq);
    int warp = t >> 5, lane = t & 31;
    if(lane==0){ rs[warp]=ws; rq[warp]=wq; }
    __syncthreads();
    if(warp==0){
        float a = (lane<8)? rs[lane] : 0.f;
        float bq2 = (lane<8)? rq[lane] : 0.f;
        a = warpSum(a); bq2 = warpSum(bq2);
        if(lane==0){ rs[0]=a; rq[0]=bq2; }
    }
    __syncthreads();
    const float mean = rs[0] * (1.0f/768.0f);
    const float var  = rq[0] * (1.0f/768.0f) - mean*mean;
    const float inv  = rsqrtf(var + 1e-12f);

    #pragma unroll
    for(int i=0;i<3;i++){
        int c = t + i*256;
        float o = (v[i] - mean) * inv * g[c] + bta[c];
        op[c] = o;
        opp[(c & ~7) | permk(c & 7)] = to_tf32(o);
    }
}

// ---------------- launch -------------------------------------------------------------
extern "C" void kernel_launch(void* const* d_in, const int* in_sizes, int n_in,
                              void* d_out, int out_size)
{
    const float* hs   = (const float*)d_in[0];
    const float* mask = (const float*)d_in[1];
    const float* Wq   = (const float*)d_in[2];
    const float* bq   = (const float*)d_in[3];
    const float* Wk   = (const float*)d_in[4];
    const float* bk   = (const float*)d_in[5];
    const float* Wv   = (const float*)d_in[6];
    const float* bv   = (const float*)d_in[7];
    const float* Wo   = (const float*)d_in[8];
    const float* bo   = (const float*)d_in[9];
    const float* g1   = (const float*)d_in[10];
    const float* b1   = (const float*)d_in[11];
    const float* Wi   = (const float*)d_in[12];
    const float* bi   = (const float*)d_in[13];
    const float* Wo2  = (const float*)d_in[14];
    const float* bo2  = (const float*)d_in[15];
    const float* g2   = (const float*)d_in[16];
    const float* b2   = (const float*)d_in[17];

    float *h, *qkv, *vT, *ctx, *attn, *tmp, *inter, *rA;
    float *wqkvT, *bqkv, *woT, *wiT, *wo2T;
    cudaGetSymbolAddress((void**)&h,      g_h);
    cudaGetSymbolAddress((void**)&qkv,    g_qkv);
    cudaGetSymbolAddress((void**)&vT,     g_vT);
    cudaGetSymbolAddress((void**)&ctx,    g_ctx);
    cudaGetSymbolAddress((void**)&attn,   g_attn);
    cudaGetSymbolAddress((void**)&tmp,    g_tmp);
    cudaGetSymbolAddress((void**)&inter,  g_inter);
    cudaGetSymbolAddress((void**)&rA,     g_round);
    cudaGetSymbolAddress((void**)&wqkvT,  g_wqkvT);
    cudaGetSymbolAddress((void**)&bqkv,   g_bqkv);
    cudaGetSymbolAddress((void**)&woT,    g_woT);
    cudaGetSymbolAddress((void**)&wiT,    g_wiT);
    cudaGetSymbolAddress((void**)&wo2T,   g_wo2T);

    cudaFuncSetAttribute(mma_gemm<128,2>, cudaFuncAttributeMaxDynamicSharedMemorySize, SM128);
    cudaFuncSetAttribute(mma_gemm<128,1>, cudaFuncAttributeMaxDynamicSharedMemorySize, SM128);
    cudaFuncSetAttribute(mma_gemm<64,0>,  cudaFuncAttributeMaxDynamicSharedMemorySize, SM64);
    cudaFuncSetAttribute(flash_attn,      cudaFuncAttributeMaxDynamicSharedMemorySize, FL_SMEM);

    transpose_round<<<dim3(HH/32,  HH/32,  LAYERS), dim3(32,8)>>>(Wq,  wqkvT, HH,  HH,  (size_t)QKVS*HH, 0);
    transpose_round<<<dim3(HH/32,  HH/32,  LAYERS), dim3(32,8)>>>(Wk,  wqkvT, HH,  HH,  (size_t)QKVS*HH, KOFF);
    transpose_round<<<dim3(HH/32,  HH/32,  LAYERS), dim3(32,8)>>>(Wv,  wqkvT, HH,  HH,  (size_t)QKVS*HH, VOFF);
    transpose_round<<<dim3(HH/32,  HH/32,  LAYERS), dim3(32,8)>>>(Wo,  woT,   HH,  HH,  (size_t)HH*HH,   0);
    transpose_round<<<dim3(FFD/32, HH/32,  LAYERS), dim3(32,8)>>>(Wi,  wiT,   HH,  FFD, (size_t)HH*FFD,  0);
    transpose_round<<<dim3(HH/32,  FFD/32, LAYERS), dim3(32,8)>>>(Wo2, wo2T,  FFD, HH,  (size_t)FFD*HH,  0);
    concat_bias<<<(LAYERS*HH+255)/256, 256>>>(bq, bk, bv, bqkv);

    const int nH = M_TOK*HH;
    copy_kernel<<<(nH+255)/256, 256>>>(h, hs, nH);
    round_perm<<<(nH+255)/256, 256>>>(rA, hs, nH);

    dim3 gQKV(QKVS/128, M_TOK/128);
    dim3 gFF1(FFD/128,  M_TOK/128);
    dim3 gN64(HH/64,    M_TOK/128);

    for(int l=0; l<LAYERS; l++){
        const float* lbo  = bo  + (size_t)l*HH;
        const float* lbi  = bi  + (size_t)l*FFD;
        const float* lbo2 = bo2 + (size_t)l*HH;
        const float* lg1  = g1  + (size_t)l*HH;
        const float* lb1  = b1  + (size_t)l*HH;
        const float* lg2  = g2  + (size_t)l*HH;
        const float* lb2  = b2  + (size_t)l*HH;

        mma_gemm<128,2><<<gQKV, 256, SM128>>>(
            rA, wqkvT + (size_t)l*QKVS*HH, bqkv + (size_t)l*QKVS, qkv, vT, QKVS, HH);

        flash_attn<<<dim3(4, BB*NHD), 256, FL_SMEM>>>(qkv, vT, mask, ctx);

        mma_gemm<64,0><<<gN64, 128, SM64>>>(
            ctx, woT + (size_t)l*HH*HH, lbo, tmp, nullptr, HH, HH);
        add_layernorm_dual<<<M_TOK, 256>>>(tmp, h, lg1, lb1, attn, rA);

        mma_gemm<128,1><<<gFF1, 256, SM128>>>(
            rA, wiT + (size_t)l*HH*FFD, lbi, inter, nullptr, FFD, HH);
        mma_gemm<64,0><<<gN64, 128, SM64>>>(
            inter, wo2T + (size_t)l*FFD*HH, lbo2, tmp, nullptr, HH, FFD);
        add_layernorm_dual<<<M_TOK, 256>>>(tmp, attn, lg2, lb2,
                                           (l==LAYERS-1) ? (float*)d_out : h, rA);
    }
}

// round 6
// speedup vs baseline: 3.7881x; 1.3403x over previous
#include <cuda_runtime.h>
#include <math.h>
#include <stdint.h>

#define LAYERS 12
#define BB 8
#define SS 512
#define HH 768
#define NHD 12
#define DHD 64
#define FFD 3072
#define M_TOK (BB*SS)   // 4096
#define QKVS 2304
#define KOFF 768
#define VOFF 1536

// ---------------- scratch -----------------------------------------------------
__device__ float g_h[M_TOK*HH];
__device__ float g_qkv[M_TOK*QKVS];
__device__ float g_vT[BB*NHD*DHD*SS];      // [bh*64+d][s]
__device__ float g_ctx[M_TOK*HH];
__device__ float g_attn[M_TOK*HH];
__device__ float g_tmp[M_TOK*HH];
__device__ float g_round[M_TOK*HH];
__device__ float g_inter[M_TOK*FFD];

__device__ float g_wqkvT[LAYERS*QKVS*HH];
__device__ float g_bqkv [LAYERS*QKVS];
__device__ float g_woT  [LAYERS*HH*HH];
__device__ float g_wiT  [LAYERS*HH*FFD];
__device__ float g_wo2T [LAYERS*FFD*HH];

// ---------------- helpers -----------------------------------------------------
__inline__ __device__ float warpSum(float v){
    #pragma unroll
    for(int o=16;o;o>>=1) v += __shfl_xor_sync(0xffffffffu, v, o);
    return v;
}
__device__ __forceinline__ float gelu_exact(float x){
    return 0.5f * x * (1.0f + erff(x * 0.70710678118654752440f));
}
__device__ __forceinline__ float to_tf32(float x){
    uint32_t r;
    asm("cvt.rn.tf32.f32 %0, %1;" : "=r"(r) : "f"(x));
    return __uint_as_float(r);
}
__device__ __forceinline__ uint32_t s2u(const void* p){
    uint32_t a;
    asm("{ .reg .u64 t; cvta.to.shared.u64 t, %1; cvt.u32.u64 %0, t; }" : "=r"(a) : "l"(p));
    return a;
}
__device__ __forceinline__ int permk(int j){ return ((j&3)<<1) | (j>>2); }

// exp(x) for x <= 0 on the FMA/ALU pipes (no MUFU). rel err ~3e-6.
__device__ __forceinline__ float exp_fma(float x){
    x = fmaxf(x, -80.0f);
    float y  = x * 1.44269504088896341f;
    float nm = y + 12582912.0f;
    float n  = nm - 12582912.0f;
    float f  = y - n;
    float p  = 1.3333558146428443e-3f;
    p = fmaf(p, f, 9.6181291851826464e-3f);
    p = fmaf(p, f, 5.5504108664821580e-2f);
    p = fmaf(p, f, 2.4022650695910071e-1f);
    p = fmaf(p, f, 6.9314718055994531e-1f);
    p = fmaf(p, f, 1.0f);
    int e = __float_as_int(nm) + (127 - 0x4B400000);
    return p * __int_as_float(e << 23);
}

#define CP_ASYNC16(dst, src) \
    asm volatile("cp.async.cg.shared.global [%0], [%1], 16;" :: "r"(dst), "l"(src))
#define CP_COMMIT() asm volatile("cp.async.commit_group;")
#define CP_WAIT(N)  asm volatile("cp.async.wait_group %0;" :: "n"(N) : "memory")

__device__ __forceinline__ void mma_tf32(float* d, const uint32_t* a, const uint32_t* b){
    asm volatile(
        "mma.sync.aligned.m16n8k8.row.col.f32.tf32.tf32.f32 "
        "{%0,%1,%2,%3}, {%4,%5,%6,%7}, {%8,%9}, {%0,%1,%2,%3};"
        : "+f"(d[0]), "+f"(d[1]), "+f"(d[2]), "+f"(d[3])
        : "r"(a[0]), "r"(a[1]), "r"(a[2]), "r"(a[3]), "r"(b[0]), "r"(b[1]));
}

// ---------------- elementwise ---------------------------------------------------
__global__ void round_perm(float* __restrict__ dst, const float* __restrict__ src, int n){
    int i = blockIdx.x*blockDim.x + threadIdx.x;
    if(i < n) dst[(i & ~7) | permk(i & 7)] = to_tf32(src[i]);
}
__global__ void concat_bias(const float* __restrict__ bq, const float* __restrict__ bk,
                            const float* __restrict__ bv, float* __restrict__ bqkv){
    int i = blockIdx.x*blockDim.x + threadIdx.x;
    if(i < LAYERS*HH){
        int l = i / HH, c = i % HH;
        bqkv[(size_t)l*QKVS + c]        = bq[i];
        bqkv[(size_t)l*QKVS + KOFF + c] = bk[i];
        bqkv[(size_t)l*QKVS + VOFF + c] = bv[i];
    }
}
__global__ void transpose_round(const float* __restrict__ W, float* __restrict__ WT,
                                int K, int N, size_t outLS, int rowOff){
    __shared__ float ts[32][33];
    const int l = blockIdx.z;
    const float* Wl = W + (size_t)l*K*N;
    float* WTl = WT + (size_t)l*outLS;
    const int n0 = blockIdx.x*32, k0 = blockIdx.y*32;
    const int tx = threadIdx.x, ty = threadIdx.y;
    #pragma unroll
    for(int i=0;i<4;i++)
        ts[ty+i*8][tx] = Wl[(size_t)(k0+ty+i*8)*N + n0 + tx];
    __syncthreads();
    const int pk = (tx & 24) | permk(tx & 7);
    #pragma unroll
    for(int i=0;i<4;i++)
        WTl[(size_t)(rowOff + n0+ty+i*8)*K + k0 + pk] = to_tf32(ts[tx][ty+i*8]);
}

// ---------------- TF32 GEMM (XOR-swizzled smem, 1 barrier/iter) ------------------
// MODE 0: +bias. MODE 1: gelu + round + K-perm store. MODE 2: QKV epilogue.
#define BK 32
#define GSTAGES 3
#define SM128 ((GSTAGES*(128+128)*32)*4)   // 98304
#define SM64  ((GSTAGES*(128+ 64)*32)*4)   // 73728

template<int BN, int MODE>
__global__ __launch_bounds__(BN==128 ? 256 : 128, BN==128 ? 2 : 3)
void mma_gemm(const float* __restrict__ A, const float* __restrict__ Wt,
              const float* __restrict__ bias, float* __restrict__ C,
              float* __restrict__ vT, int N, int K)
{
    constexpr int THREADS = (BN==128) ? 256 : 128;
    extern __shared__ float sm[];
    float* Asm = sm;                      // [GSTAGES][128][32] swizzled
    float* Wsm = sm + GSTAGES*128*32;     // [GSTAGES][BN][32]

    const int tid  = threadIdx.x;
    const int wid  = tid >> 5;
    const int lane = tid & 31;
    const int m0 = blockIdx.y * 128;
    const int n0 = blockIdx.x * BN;
    const int wm = (BN==128) ? (wid >> 1) * 32 : wid * 32;
    const int wn = (BN==128) ? (wid & 1) * 64 : 0;
    const int g  = lane >> 5 ? 0 : (lane >> 2);
    const int t4 = lane & 3;
    const int xr = (g & 3) << 3;          // fragment-load swizzle
    const int KT = K / BK;

    const float* Ag = A  + (size_t)m0 * K;
    const float* Wg = Wt + (size_t)n0 * K;

    auto load_tile = [&](int t){
        const int s = t % GSTAGES;
        float* as = Asm + s*128*32;
        float* ws = Wsm + s*BN*32;
        #pragma unroll
        for(int l=0;l<1024/THREADS;l++){
            const int c = tid + l*THREADS;
            const int row = c >> 3, k4 = c & 7;
            const int w = (k4*4) ^ ((row & 3) << 3);
            CP_ASYNC16(s2u(as + row*32 + w), Ag + (size_t)row*K + t*BK + k4*4);
        }
        #pragma unroll
        for(int l=0;l<(BN*8)/THREADS;l++){
            const int c = tid + l*THREADS;
            const int row = c >> 3, k4 = c & 7;
            const int w = (k4*4) ^ ((row & 3) << 3);
            CP_ASYNC16(s2u(ws + row*32 + w), Wg + (size_t)row*K + t*BK + k4*4);
        }
        CP_COMMIT();
    };

    float acc[2][8][4];
    #pragma unroll
    for(int mi=0;mi<2;mi++)
        #pragma unroll
        for(int ni=0;ni<8;ni++)
            #pragma unroll
            for(int r=0;r<4;r++) acc[mi][ni][r] = 0.f;

    load_tile(0);
    load_tile(1);

    for(int t=0; t<KT; t++){
        if (t == KT-1) CP_WAIT(0); else CP_WAIT(1);
        __syncthreads();
        if (t+2 < KT) load_tile(t+2);

        const float* as = Asm + (t % GSTAGES)*128*32;
        const float* ws = Wsm + (t % GSTAGES)*BN*32;

        #pragma unroll
        for(int ks=0; ks<BK/8; ks++){
            const int kw = (ks*8) ^ xr;
            uint32_t a[2][4], b[8][2];
            #pragma unroll
            for(int mi=0; mi<2; mi++){
                const float* ap = as + (wm + mi*16 + g)*32 + kw + 2*t4;
                float2 lo = *(const float2*)ap;
                float2 hi = *(const float2*)(ap + 8*32);
                a[mi][0] = __float_as_uint(lo.x);
                a[mi][2] = __float_as_uint(lo.y);
                a[mi][1] = __float_as_uint(hi.x);
                a[mi][3] = __float_as_uint(hi.y);
            }
            #pragma unroll
            for(int ni=0; ni<8; ni++){
                float2 bv = *(const float2*)(ws + (wn + ni*8 + g)*32 + kw + 2*t4);
                b[ni][0] = __float_as_uint(bv.x);
                b[ni][1] = __float_as_uint(bv.y);
            }
            #pragma unroll
            for(int mi=0; mi<2; mi++)
                #pragma unroll
                for(int ni=0; ni<8; ni++)
                    mma_tf32(acc[mi][ni], a[mi], b[ni]);
        }
        // no trailing barrier: next iteration's wait+sync fences WAR
    }

    if (MODE == 2 && n0 >= VOFF){
        // V: round + transpose into vT[(b*768 + c-1536)][s]
        __syncthreads();
        float* stage = sm + wid*2304;   // [64 d][36]
        #pragma unroll
        for(int mi=0; mi<2; mi++){
            #pragma unroll
            for(int ni=0; ni<8; ni++){
                const int cl = ni*8 + 2*t4;
                const int sl = mi*16 + g;
                const float b0 = bias[n0+wn+cl], b1 = bias[n0+wn+cl+1];
                stage[(cl  )*36 + sl  ] = to_tf32(acc[mi][ni][0] + b0);
                stage[(cl+1)*36 + sl  ] = to_tf32(acc[mi][ni][1] + b1);
                stage[(cl  )*36 + sl+8] = to_tf32(acc[mi][ni][2] + b0);
                stage[(cl+1)*36 + sl+8] = to_tf32(acc[mi][ni][3] + b1);
            }
        }
        __syncwarp();
        const int b    = m0 >> 9;
        const int soff = (m0 + wm) & 511;
        #pragma unroll
        for(int t=0; t<16; t++){
            const int chunk = lane + t*32;
            const int dr = chunk >> 3, c4 = chunk & 7;
            float4 val = *(const float4*)(stage + dr*36 + c4*4);
            *(float4*)(vT + ((size_t)(b*768 + (n0 - VOFF) + wn + dr))*512 + soff + c4*4) = val;
        }
        return;
    }

    #pragma unroll
    for(int mi=0; mi<2; mi++){
        #pragma unroll
        for(int ni=0; ni<8; ni++){
            const int r = m0 + wm + mi*16 + g;
            const int c = n0 + wn + ni*8 + 2*t4;
            const float bx = bias[c], by = bias[c+1];
            float v0 = acc[mi][ni][0] + bx;
            float v1 = acc[mi][ni][1] + by;
            float v2 = acc[mi][ni][2] + bx;
            float v3 = acc[mi][ni][3] + by;
            if (MODE == 1){
                v0 = gelu_exact(v0); v1 = gelu_exact(v1);
                v2 = gelu_exact(v2); v3 = gelu_exact(v3);
            }
            if (MODE == 2){
                const float sc = (n0 < KOFF) ? 0.125f : 1.0f;
                v0 *= sc; v1 *= sc; v2 *= sc; v3 *= sc;
            }
            if (MODE == 1 || MODE == 2){
                const int base8 = c & ~7;
                const int p0 = base8 + permk(2*t4);
                const int p1 = base8 + permk(2*t4 + 1);
                C[(size_t)r*N + p0]     = to_tf32(v0);
                C[(size_t)r*N + p1]     = to_tf32(v1);
                C[(size_t)(r+8)*N + p0] = to_tf32(v2);
                C[(size_t)(r+8)*N + p1] = to_tf32(v3);
            } else {
                *(float2*)(C + (size_t)r*N + c)     = make_float2(v0, v1);
                *(float2*)(C + (size_t)(r+8)*N + c) = make_float2(v2, v3);
            }
        }
    }
}

// ---------------- fused flash attention (tf32 mma) -------------------------------
#define FL_SMEM 112640

__global__ __launch_bounds__(256, 2)
void flash_attn(const float* __restrict__ qkv, const float* __restrict__ vT,
                const float* __restrict__ mask, float* __restrict__ ctx)
{
    extern __shared__ float fs[];
    float* Qs  = fs;              // [128][72]
    float* Ksm = fs + 9216;       // [2][64][72]
    float* Vsm = fs + 18432;      // [2][64][72]
    float* msk = fs + 27648;      // [512]

    const int tid  = threadIdx.x;
    const int wid  = tid >> 5;
    const int lane = tid & 31;
    const int g  = lane >> 2;
    const int t4 = lane & 3;
    const int qt = blockIdx.x;
    const int bh = blockIdx.y;
    const int b    = bh / NHD;
    const int head = bh % NHD;

    const float* Qg = qkv + ((size_t)(b*SS + qt*128))*QKVS + head*DHD;
    const float* Kg = qkv + ((size_t)(b*SS))*QKVS + KOFF + head*DHD;
    const float* Vg = vT  + ((size_t)(b*HH + head*DHD))*SS;

    if (tid < 128)
        *(float4*)(msk + tid*4) = *(const float4*)(mask + b*SS + tid*4);

    #pragma unroll
    for(int i=0;i<8;i++){
        const int c = tid + i*256;
        const int row = c >> 4, c4 = c & 15;
        CP_ASYNC16(s2u(Qs + row*72 + c4*4), Qg + (size_t)row*QKVS + c4*4);
    }
    CP_COMMIT();

    auto load_kv = [&](int kt){
        float* ks = Ksm + (kt&1)*4608;
        float* vs = Vsm + (kt&1)*4608;
        #pragma unroll
        for(int i=0;i<4;i++){
            const int c = tid + i*256;
            const int row = c >> 4, c4 = c & 15;
            CP_ASYNC16(s2u(ks + row*72 + c4*4), Kg + (size_t)(kt*64+row)*QKVS + c4*4);
            CP_ASYNC16(s2u(vs + row*72 + c4*4), Vg + (size_t)row*SS + kt*64 + c4*4);
        }
        CP_COMMIT();
    };
    load_kv(0);
    load_kv(1);

    float ctxa[8][4];
    #pragma unroll
    for(int dt=0;dt<8;dt++)
        #pragma unroll
        for(int r=0;r<4;r++) ctxa[dt][r]=0.f;
    float m0=-1e30f, m1=-1e30f, l0=0.f, l1=0.f;

    const float* qb = Qs + (wid*16 + g)*72 + 2*t4;

    for(int kt=0; kt<8; kt++){
        if (kt < 7) CP_WAIT(1); else CP_WAIT(0);
        __syncthreads();

        const float* ks = Ksm + (kt&1)*4608;
        const float* vs = Vsm + (kt&1)*4608;

        float sacc[8][4];
        #pragma unroll
        for(int nt=0;nt<8;nt++)
            #pragma unroll
            for(int r=0;r<4;r++) sacc[nt][r]=0.f;

        #pragma unroll
        for(int ksi=0; ksi<8; ksi++){
            uint32_t a[4];
            float2 qlo = *(const float2*)(qb + ksi*8);
            float2 qhi = *(const float2*)(qb + 8*72 + ksi*8);
            a[0] = __float_as_uint(qlo.x);
            a[1] = __float_as_uint(qhi.x);
            a[2] = __float_as_uint(qlo.y);
            a[3] = __float_as_uint(qhi.y);
            #pragma unroll
            for(int nt=0; nt<8; nt++){
                float2 bv = *(const float2*)(ks + (nt*8+g)*72 + ksi*8 + 2*t4);
                uint32_t br[2] = { __float_as_uint(bv.x), __float_as_uint(bv.y) };
                mma_tf32(sacc[nt], a, br);
            }
        }

        float r0 = -1e30f, r1 = -1e30f;
        #pragma unroll
        for(int nt=0; nt<8; nt++){
            const float mk0 = msk[kt*64 + nt*8 + 2*t4];
            const float mk1 = msk[kt*64 + nt*8 + 2*t4 + 1];
            sacc[nt][0] += mk0; sacc[nt][1] += mk1;
            sacc[nt][2] += mk0; sacc[nt][3] += mk1;
            r0 = fmaxf(r0, fmaxf(sacc[nt][0], sacc[nt][1]));
            r1 = fmaxf(r1, fmaxf(sacc[nt][2], sacc[nt][3]));
        }
        r0 = fmaxf(r0, __shfl_xor_sync(0xffffffffu, r0, 1));
        r0 = fmaxf(r0, __shfl_xor_sync(0xffffffffu, r0, 2));
        r1 = fmaxf(r1, __shfl_xor_sync(0xffffffffu, r1, 1));
        r1 = fmaxf(r1, __shfl_xor_sync(0xffffffffu, r1, 2));

        const float mn0 = fmaxf(m0, r0);
        const float mn1 = fmaxf(m1, r1);
        const float al0 = exp_fma(m0 - mn0);
        const float al1 = exp_fma(m1 - mn1);
        m0 = mn0; m1 = mn1;
        l0 *= al0; l1 *= al1;
        #pragma unroll
        for(int dt=0; dt<8; dt++){
            ctxa[dt][0] *= al0; ctxa[dt][1] *= al0;
            ctxa[dt][2] *= al1; ctxa[dt][3] *= al1;
        }

        float ps0 = 0.f, ps1 = 0.f;
        #pragma unroll
        for(int nt=0; nt<8; nt++){
            sacc[nt][0] = to_tf32(exp_fma(sacc[nt][0]-mn0)); ps0 += sacc[nt][0];
            sacc[nt][1] = to_tf32(exp_fma(sacc[nt][1]-mn0)); ps0 += sacc[nt][1];
            sacc[nt][2] = to_tf32(exp_fma(sacc[nt][2]-mn1)); ps1 += sacc[nt][2];
            sacc[nt][3] = to_tf32(exp_fma(sacc[nt][3]-mn1)); ps1 += sacc[nt][3];
        }
        l0 += ps0; l1 += ps1;

        #pragma unroll
        for(int dt=0; dt<8; dt++){
            #pragma unroll
            for(int ksi=0; ksi<8; ksi++){
                float2 bv = *(const float2*)(vs + (dt*8+g)*72 + ksi*8 + 2*t4);
                uint32_t br[2] = { __float_as_uint(bv.x), __float_as_uint(bv.y) };
                uint32_t a[4] = { __float_as_uint(sacc[ksi][0]),
                                  __float_as_uint(sacc[ksi][2]),
                                  __float_as_uint(sacc[ksi][1]),
                                  __float_as_uint(sacc[ksi][3]) };
                mma_tf32(ctxa[dt], a, br);
            }
        }
        __syncthreads();
        if (kt + 2 < 8) load_kv(kt + 2);
    }

    l0 += __shfl_xor_sync(0xffffffffu, l0, 1);
    l0 += __shfl_xor_sync(0xffffffffu, l0, 2);
    l1 += __shfl_xor_sync(0xffffffffu, l1, 1);
    l1 += __shfl_xor_sync(0xffffffffu, l1, 2);
    const float inv0 = 1.0f / l0;
    const float inv1 = 1.0f / l1;

    const int token0 = b*SS + qt*128 + wid*16 + g;
    float* o0 = ctx + (size_t)token0*HH + head*DHD;
    float* o1 = o0 + (size_t)8*HH;
    #pragma unroll
    for(int dt=0; dt<8; dt++){
        const int p0 = dt*8 + permk(2*t4);
        const int p1 = dt*8 + permk(2*t4 + 1);
        o0[p0] = to_tf32(ctxa[dt][0] * inv0);
        o0[p1] = to_tf32(ctxa[dt][1] * inv0);
        o1[p0] = to_tf32(ctxa[dt][2] * inv1);
        o1[p1] = to_tf32(ctxa[dt][3] * inv1);
    }
}

// ---------------- add residual + layernorm (dual output) --------------------------
__global__ __launch_bounds__(256)
void add_layernorm_dual(const float* __restrict__ x, const float* __restrict__ res,
                        const float* __restrict__ g, const float* __restrict__ bta,
                        float* __restrict__ out, float* __restrict__ outp)
{
    const int tok = blockIdx.x;
    const float* xp = x   + (size_t)tok*HH;
    const float* rp = res + (size_t)tok*HH;
    float* op  = out  + (size_t)tok*HH;
    float* opp = outp + (size_t)tok*HH;
    const int t = threadIdx.x;

    float v[3];
    float s = 0.f, sq = 0.f;
    #pragma unroll
    for(int i=0;i<3;i++){
        int c = t + i*256;
        float val = xp[c] + rp[c];
        v[i] = val; s += val; sq += val*val;
    }

    __shared__ float rs[8], rq[8];
    float ws = warpSum(s), wq = warpSum(sq);
    int warp = t >> 5, lane = t & 31;
    if(lane==0){ rs[warp]=ws; rq[warp]=wq; }
    __syncthreads();
    if(warp==0){
        float a = (lane<8)? rs[lane] : 0.f;
        float bq2 = (lane<8)? rq[lane] : 0.f;
        a = warpSum(a); bq2 = warpSum(bq2);
        if(lane==0){ rs[0]=a; rq[0]=bq2; }
    }
    __syncthreads();
    const float mean = rs[0] * (1.0f/768.0f);
    const float var  = rq[0] * (1.0f/768.0f) - mean*mean;
    const float inv  = rsqrtf(var + 1e-12f);

    #pragma unroll
    for(int i=0;i<3;i++){
        int c = t + i*256;
        float o = (v[i] - mean) * inv * g[c] + bta[c];
        op[c] = o;
        opp[(c & ~7) | permk(c & 7)] = to_tf32(o);
    }
}

// ---------------- launch -------------------------------------------------------------
extern "C" void kernel_launch(void* const* d_in, const int* in_sizes, int n_in,
                              void* d_out, int out_size)
{
    const float* hs   = (const float*)d_in[0];
    const float* mask = (const float*)d_in[1];
    const float* Wq   = (const float*)d_in[2];
    const float* bq   = (const float*)d_in[3];
    const float* Wk   = (const float*)d_in[4];
    const float* bk   = (const float*)d_in[5];
    const float* Wv   = (const float*)d_in[6];
    const float* bv   = (const float*)d_in[7];
    const float* Wo   = (const float*)d_in[8];
    const float* bo   = (const float*)d_in[9];
    const float* g1   = (const float*)d_in[10];
    const float* b1   = (const float*)d_in[11];
    const float* Wi   = (const float*)d_in[12];
    const float* bi   = (const float*)d_in[13];
    const float* Wo2  = (const float*)d_in[14];
    const float* bo2  = (const float*)d_in[15];
    const float* g2   = (const float*)d_in[16];
    const float* b2   = (const float*)d_in[17];

    float *h, *qkv, *vT, *ctx, *attn, *tmp, *inter, *rA;
    float *wqkvT, *bqkv, *woT, *wiT, *wo2T;
    cudaGetSymbolAddress((void**)&h,      g_h);
    cudaGetSymbolAddress((void**)&qkv,    g_qkv);
    cudaGetSymbolAddress((void**)&vT,     g_vT);
    cudaGetSymbolAddress((void**)&ctx,    g_ctx);
    cudaGetSymbolAddress((void**)&attn,   g_attn);
    cudaGetSymbolAddress((void**)&tmp,    g_tmp);
    cudaGetSymbolAddress((void**)&inter,  g_inter);
    cudaGetSymbolAddress((void**)&rA,     g_round);
    cudaGetSymbolAddress((void**)&wqkvT,  g_wqkvT);
    cudaGetSymbolAddress((void**)&bqkv,   g_bqkv);
    cudaGetSymbolAddress((void**)&woT,    g_woT);
    cudaGetSymbolAddress((void**)&wiT,    g_wiT);
    cudaGetSymbolAddress((void**)&wo2T,   g_wo2T);

    cudaFuncSetAttribute(mma_gemm<128,2>, cudaFuncAttributeMaxDynamicSharedMemorySize, SM128);
    cudaFuncSetAttribute(mma_gemm<128,1>, cudaFuncAttributeMaxDynamicSharedMemorySize, SM128);
    cudaFuncSetAttribute(mma_gemm<64,0>,  cudaFuncAttributeMaxDynamicSharedMemorySize, SM64);
    cudaFuncSetAttribute(flash_attn,      cudaFuncAttributeMaxDynamicSharedMemorySize, FL_SMEM);

    transpose_round<<<dim3(HH/32,  HH/32,  LAYERS), dim3(32,8)>>>(Wq,  wqkvT, HH,  HH,  (size_t)QKVS*HH, 0);
    transpose_round<<<dim3(HH/32,  HH/32,  LAYERS), dim3(32,8)>>>(Wk,  wqkvT, HH,  HH,  (size_t)QKVS*HH, KOFF);
    transpose_round<<<dim3(HH/32,  HH/32,  LAYERS), dim3(32,8)>>>(Wv,  wqkvT, HH,  HH,  (size_t)QKVS*HH, VOFF);
    transpose_round<<<dim3(HH/32,  HH/32,  LAYERS), dim3(32,8)>>>(Wo,  woT,   HH,  HH,  (size_t)HH*HH,   0);
    transpose_round<<<dim3(FFD/32, HH/32,  LAYERS), dim3(32,8)>>>(Wi,  wiT,   HH,  FFD, (size_t)HH*FFD,  0);
    transpose_round<<<dim3(HH/32,  FFD/32, LAYERS), dim3(32,8)>>>(Wo2, wo2T,  FFD, HH,  (size_t)FFD*HH,  0);
    concat_bias<<<(LAYERS*HH+255)/256, 256>>>(bq, bk, bv, bqkv);

    const int nH = M_TOK*HH;
    round_perm<<<(nH+255)/256, 256>>>(rA, hs, nH);

    dim3 gQKV(QKVS/128, M_TOK/128);
    dim3 gFF1(FFD/128,  M_TOK/128);
    dim3 gN64(HH/64,    M_TOK/128);

    for(int l=0; l<LAYERS; l++){
        const float* lbo  = bo  + (size_t)l*HH;
        const float* lbi  = bi  + (size_t)l*FFD;
        const float* lbo2 = bo2 + (size_t)l*HH;
        const float* lg1  = g1  + (size_t)l*HH;
        const float* lb1  = b1  + (size_t)l*HH;
        const float* lg2  = g2  + (size_t)l*HH;
        const float* lb2  = b2  + (size_t)l*HH;
        const float* lres = (l == 0) ? hs : h;

        mma_gemm<128,2><<<gQKV, 256, SM128>>>(
            rA, wqkvT + (size_t)l*QKVS*HH, bqkv + (size_t)l*QKVS, qkv, vT, QKVS, HH);

        flash_attn<<<dim3(4, BB*NHD), 256, FL_SMEM>>>(qkv, vT, mask, ctx);

        mma_gemm<64,0><<<gN64, 128, SM64>>>(
            ctx, woT + (size_t)l*HH*HH, lbo, tmp, nullptr, HH, HH);
        add_layernorm_dual<<<M_TOK, 256>>>(tmp, lres, lg1, lb1, attn, rA);

        mma_gemm<128,1><<<gFF1, 256, SM128>>>(
            rA, wiT + (size_t)l*HH*FFD, lbi, inter, nullptr, FFD, HH);
        mma_gemm<64,0><<<gN64, 128, SM64>>>(
            inter, wo2T + (size_t)l*FFD*HH, lbo2, tmp, nullptr, HH, FFD);
        add_layernorm_dual<<<M_TOK, 256>>>(tmp, attn, lg2, lb2,
                                           (l==LAYERS-1) ? (float*)d_out : h, rA);
    }
}